// round 9
// baseline (speedup 1.0000x reference)
#include <cuda_runtime.h>

#define TT    65536
#define NB4   16384          /* 4*NB4 = 65536 serial 4-step blocks */
#define SD    100
#define HID   8
#define NOBS  12
#define DTC   0.01f
#define SW    132            /* state width */
#define GQ    8
#define PRE_CTAS  (NB4 / GQ) /* 2048, exact */
#define POST_CTAS (NB4 / GQ) /* 2048, exact */

__device__ __forceinline__ unsigned long long pack2(float lo, float hi) {
    unsigned long long r;
    asm("mov.b64 %0, {%1, %2};" : "=l"(r) : "f"(lo), "f"(hi));
    return r;
}
__device__ __forceinline__ void unpack2(unsigned long long v, float& lo, float& hi) {
    asm("mov.b64 {%0, %1}, %2;" : "=f"(lo), "=f"(hi) : "l"(v));
}
__device__ __forceinline__ void fma2(unsigned long long& acc, unsigned long long a, unsigned long long b) {
    asm("fma.rn.f32x2 %0, %1, %2, %0;" : "+l"(acc) : "l"(a), "l"(b));
}
__device__ __forceinline__ void add2(unsigned long long& acc, unsigned long long b) {
    asm("add.rn.f32x2 %0, %0, %1;" : "+l"(acc) : "l"(b));
}
__device__ __forceinline__ float tanh_hw(float x) {
    float r;
    asm("tanh.approx.f32 %0, %1;" : "=f"(r) : "f"(x));
    return r;
}

// ------------------------- device scratch -------------------------
__device__ float g_R[132 * SW];          // rows 0-99: c-rows; 100-131: chain rows
__device__ float g_At4[SD * SD];         // A in float4-interleaved matvec layout
__device__ float g_U1[SD * HID];         // dt A W2
__device__ float g_U2[SD * HID];         // dt A^2 W2
__device__ float g_V[7 * 64];            // V_j = dt W1 A^j W2, j=0..6
__device__ float g_P4[(size_t)NB4 * SD];
__device__ float g_Qq[(size_t)NB4 * 32]; // q0|q1|q2|q3 per block
__device__ float g_G[(size_t)(NB4 + 1) * SD];   // anchors c_{4b} (row 0 = c0)
__device__ float g_h[(size_t)(TT + 9) * HID];   // h_t rows

// ============================================================================
// 1a) setup1 (1 CTA): c-rows [A^4 | dtA^3W2 | dtA^2W2 | dtAW2 | dtW2],
//     At4 layout, initial rollout h1..h4, anchor row 0.
// ============================================================================
__global__ void __launch_bounds__(128, 1) setup1_kernel(
    const float* __restrict__ A,  const float* __restrict__ Bw,
    const float* __restrict__ W1, const float* __restrict__ b1,
    const float* __restrict__ W2, const float* __restrict__ b2,
    const float* __restrict__ c0, const float* __restrict__ w,
    const float* __restrict__ u)
{
    __shared__ float As[SD * SD];     // 40000 B
    __shared__ float W2d[SD * HID];   // dt*W2
    __shared__ float W1s[SD * HID];   // W1 -> U1 -> U2 staging
    __shared__ float cva[SD];
    __shared__ float cvb[SD];
    __shared__ float hh[HID];

    const int tid = threadIdx.x;

    for (int i = tid; i < SD * SD; i += 128) As[i] = A[i];
    for (int i = tid; i < SD * HID; i += 128) W2d[i] = DTC * W2[i];
    for (int i = tid; i < SD * HID; i += 128) W1s[i] = W1[i];
    if (tid < SD) { cva[tid] = c0[tid]; g_G[tid] = c0[tid]; }
    __syncthreads();
    for (int o = tid; o < SD * SD; o += 128) {
        int j4 = o / 400, rem = o % 400, i = rem / 4, r = rem % 4;
        g_At4[o] = As[i * SD + 4 * j4 + r];
    }

    // ---- initial rollout: h_t = tanh(W1 c_{t-1} + b1), c_t = A c_{t-1} + in_t + dtW2 h_t
    float* cc = cva; float* cn = cvb;
    for (int t = 1; t <= 4; t++) {
        if (tid >= 104 && tid < 112) {
            const int z = tid - 104;
            float s = b1[z];
            for (int k = 0; k < SD; k++) s += W1s[z * SD + k] * cc[k];
            float ht = tanh_hw(s);
            hh[z] = ht;
            g_h[(size_t)t * HID + z] = ht;
        }
        __syncthreads();
        if (t < 4 && tid < SD) {
            const int i = tid;
            float s = Bw[i * 2] * w[(t - 1) * 2] + Bw[i * 2 + 1] * w[(t - 1) * 2 + 1]
                    + u[(size_t)(t - 1) * SD + i] + DTC * b2[i];
            for (int j = 0; j < SD; j++) s += As[i * SD + j] * cc[j];
#pragma unroll
            for (int z = 0; z < HID; z++) s += W2d[i * HID + z] * hh[z];
            cn[i] = s;
        }
        __syncthreads();
        float* t2 = cc; cc = cn; cn = t2;
    }

    // ---- per-g-lane: A^2 -> A^3 -> A^4 rows; u1 = dtAW2 row
    float ra[SD], rb[SD];
    float u1r[HID], u2r[HID];
    if (tid < SD) {
        const int i = tid;
#pragma unroll
        for (int jj = 0; jj < SD; jj++) ra[jj] = 0.f;
#pragma unroll
        for (int z = 0; z < HID; z++) u1r[z] = 0.f;
        for (int j = 0; j < SD; j++) {
            const float a = As[i * SD + j];
#pragma unroll
            for (int jj = 0; jj < SD; jj++) ra[jj] += a * As[j * SD + jj];   // A^2 row
#pragma unroll
            for (int z = 0; z < HID; z++) u1r[z] += a * W2d[j * HID + z];
        }
#pragma unroll
        for (int z = 0; z < HID; z++) g_U1[i * HID + z] = u1r[z];
        // A^3
#pragma unroll
        for (int jj = 0; jj < SD; jj++) rb[jj] = 0.f;
        for (int j = 0; j < SD; j++) {
            const float a = ra[j];
#pragma unroll
            for (int jj = 0; jj < SD; jj++) rb[jj] += a * As[j * SD + jj];
        }
        // A^4 into ra
#pragma unroll
        for (int jj = 0; jj < SD; jj++) ra[jj] = 0.f;
        for (int j = 0; j < SD; j++) {
            const float a = rb[j];
#pragma unroll
            for (int jj = 0; jj < SD; jj++) ra[jj] += a * As[j * SD + jj];
        }
        for (int jj = 0; jj < SD; jj++) g_R[i * SW + jj] = ra[jj];
    }
    __syncthreads();
    for (int o = tid; o < SD * HID; o += 128) W1s[o] = g_U1[o];
    __syncthreads();
    // u2 = A U1 row
    if (tid < SD) {
        const int i = tid;
#pragma unroll
        for (int z = 0; z < HID; z++) u2r[z] = 0.f;
        for (int j = 0; j < SD; j++) {
            const float a = As[i * SD + j];
#pragma unroll
            for (int z = 0; z < HID; z++) u2r[z] += a * W1s[j * HID + z];
        }
#pragma unroll
        for (int z = 0; z < HID; z++) g_U2[i * HID + z] = u2r[z];
    }
    __syncthreads();
    for (int o = tid; o < SD * HID; o += 128) W1s[o] = g_U2[o];
    __syncthreads();
    // u3 = A U2 row; write tails [u3|u2|u1|u0]
    if (tid < SD) {
        const int i = tid;
        float u3r[HID];
#pragma unroll
        for (int z = 0; z < HID; z++) u3r[z] = 0.f;
        for (int j = 0; j < SD; j++) {
            const float a = As[i * SD + j];
#pragma unroll
            for (int z = 0; z < HID; z++) u3r[z] += a * W1s[j * HID + z];
        }
#pragma unroll
        for (int z = 0; z < HID; z++) {
            g_R[i * SW + 100 + z] = u3r[z];
            g_R[i * SW + 108 + z] = u2r[z];
            g_R[i * SW + 116 + z] = u1r[z];
            g_R[i * SW + 124 + z] = W2d[i * HID + z];   // u0 = dtW2 row
        }
    }
}

// ============================================================================
// 1b) setup2 (1 CTA): chain rows (W1A^{4+i} heads, V tails) + V tables.
//     Block-parallel W1 A^k chain via smem ping-pong.
// ============================================================================
__global__ void __launch_bounds__(128, 1) setup2_kernel(
    const float* __restrict__ A, const float* __restrict__ W1,
    const float* __restrict__ W2)
{
    __shared__ float As[SD * SD];
    __shared__ float bufA[SD * HID];
    __shared__ float bufB[SD * HID];

    const int tid = threadIdx.x;
    for (int i = tid; i < SD * SD; i += 128) As[i] = A[i];
    for (int i = tid; i < SD * HID; i += 128) bufA[i] = W1[i];   // cur = W1 (layout [z][j])
    __syncthreads();

    float* cur = bufA;
    float* nxt = bufB;

    // V0 = dt * W1 W2
    for (int o = tid; o < 64; o += 128) {
        const int z = o >> 3, zz = o & 7;
        float s = 0.f;
        for (int j = 0; j < SD; j++) s += cur[z * SD + j] * (DTC * W2[j * HID + zz]);
        g_V[o] = s;
    }
    __syncthreads();

    for (int k = 1; k <= 7; k++) {
        // nxt = cur * A
        for (int o = tid; o < SD * HID; o += 128) {
            const int z = o / SD, jj = o % SD;
            float s = 0.f;
            for (int j = 0; j < SD; j++) s += cur[z * SD + j] * As[j * SD + jj];
            nxt[o] = s;
        }
        __syncthreads();
        float* t = cur; cur = nxt; nxt = t;
        // heads for k >= 4: row 100 + 8*(k-4) + z
        if (k >= 4) {
            for (int o = tid; o < SD * HID; o += 128) {
                const int z = o / SD, jj = o % SD;
                g_R[(size_t)(100 + 8 * (k - 4) + z) * SW + jj] = cur[o];
            }
        }
        // V_k for k <= 6
        if (k <= 6) {
            for (int o = tid; o < 64; o += 128) {
                const int z = o >> 3, zz = o & 7;
                float s = 0.f;
                for (int j = 0; j < SD; j++) s += cur[z * SD + j] * (DTC * W2[j * HID + zz]);
                g_V[k * 64 + o] = s;
            }
        }
        __syncthreads();
    }

    // tails: row 100+l (l = 8i+z), col 100 + 8m + zz = V_{3+i-m}[z][zz]
    for (int o = tid; o < 32 * 32; o += 128) {
        const int l = o >> 5, cidx = o & 31;
        const int m = cidx >> 3, zz = cidx & 7;
        const int i = l >> 3, z = l & 7;
        const int d = 3 + i - m;   // 0..6
        g_R[(size_t)(100 + l) * SW + 100 + cidx] = g_V[d * 64 + z * HID + zz];
    }
}

// float4 matvec: out_i = sum_j A[i][j] v[j]
__device__ __forceinline__ float matvec100(const float4* at4s, const float4* v4, int i) {
    float acc = 0.f;
#pragma unroll
    for (int j4 = 0; j4 < 25; j4++) {
        float4 m = at4s[j4 * SD + i];
        float4 x = v4[j4];
        acc = fmaf(m.x, x.x, acc); acc = fmaf(m.y, x.y, acc);
        acc = fmaf(m.z, x.z, acc); acc = fmaf(m.w, x.w, acc);
    }
    return acc;
}

// ============================================================================
// 2) precomp: P_b (input composite for c_{4b+4}) and q0..q3 (for h_{4b+5..8})
// ============================================================================
__global__ void __launch_bounds__(128, 1) precomp_kernel(
    const float* __restrict__ w, const float* __restrict__ u,
    const float* __restrict__ Bw, const float* __restrict__ W1,
    const float* __restrict__ b1, const float* __restrict__ b2)
{
    __shared__ __align__(16) float4 at4s[SD * 25];
    __shared__ float W1sm[SD * HID];
    __shared__ __align__(16) float va[SD];
    __shared__ __align__(16) float vb[SD];

    const int tid = threadIdx.x;
    const float4* gAt4 = reinterpret_cast<const float4*>(g_At4);
    for (int o = tid; o < SD * 25; o += 128) at4s[o] = gAt4[o];
    for (int o = tid; o < SD * HID; o += 128) W1sm[o] = W1[o];

    float bwx = 0.f, bwy = 0.f, db2 = 0.f;
    if (tid < SD) { bwx = Bw[tid * 2]; bwy = Bw[tid * 2 + 1]; db2 = DTC * b2[tid]; }
    float b1z = 0.f;
    if (tid >= 104 && tid < 112) b1z = b1[tid - 104];
    __syncthreads();

    const float4* va4 = reinterpret_cast<const float4*>(va);
    const float4* vb4 = reinterpret_cast<const float4*>(vb);

    for (int gi = 0; gi < GQ; gi++) {
        const int b = blockIdx.x * GQ + gi;
        const size_t k = 4 * (size_t)b;

        // in_t helper via clamp: t <= TT
#define INW(t)  ((size_t)(((t) <= TT ? (t) : TT) - 1))
        // s0: va = in_{k+1}
        if (tid < SD)
            va[tid] = bwx * w[INW(k + 1) * 2] + bwy * w[INW(k + 1) * 2 + 1]
                    + u[INW(k + 1) * SD + tid] + db2;
        __syncthreads();
        // s1: vb = A va + in_{k+2}
        if (tid < SD)
            vb[tid] = matvec100(at4s, va4, tid)
                    + bwx * w[INW(k + 2) * 2] + bwy * w[INW(k + 2) * 2 + 1]
                    + u[INW(k + 2) * SD + tid] + db2;
        __syncthreads();
        // s2: va = A vb + in_{k+3}
        if (tid < SD)
            va[tid] = matvec100(at4s, vb4, tid)
                    + bwx * w[INW(k + 3) * 2] + bwy * w[INW(k + 3) * 2 + 1]
                    + u[INW(k + 3) * SD + tid] + db2;
        __syncthreads();
        // s3: vb = A va + in_{k+4}   (= P_b)
        if (tid < SD)
            vb[tid] = matvec100(at4s, va4, tid)
                    + bwx * w[INW(k + 4) * 2] + bwy * w[INW(k + 4) * 2 + 1]
                    + u[INW(k + 4) * SD + tid] + db2;
        __syncthreads();
        // s4: store P; va = A P + in_{k+5}; q0 = W1 P + b1
        if (tid < SD) {
            g_P4[(size_t)b * SD + tid] = vb[tid];
            va[tid] = matvec100(at4s, vb4, tid)
                    + bwx * w[INW(k + 5) * 2] + bwy * w[INW(k + 5) * 2 + 1]
                    + u[INW(k + 5) * SD + tid] + db2;
        } else if (tid >= 104 && tid < 112) {
            const int z = tid - 104;
            float s = b1z;
#pragma unroll 4
            for (int j = 0; j < SD; j++) s += W1sm[z * SD + j] * vb[j];
            g_Qq[(size_t)b * 32 + z] = s;
        }
        __syncthreads();
        // s5: vb = A va + in_{k+6}; q1 = W1 va + b1
        if (tid < SD)
            vb[tid] = matvec100(at4s, va4, tid)
                    + bwx * w[INW(k + 6) * 2] + bwy * w[INW(k + 6) * 2 + 1]
                    + u[INW(k + 6) * SD + tid] + db2;
        else if (tid >= 104 && tid < 112) {
            const int z = tid - 104;
            float s = b1z;
#pragma unroll 4
            for (int j = 0; j < SD; j++) s += W1sm[z * SD + j] * va[j];
            g_Qq[(size_t)b * 32 + 8 + z] = s;
        }
        __syncthreads();
        // s6: va = A vb + in_{k+7}; q2 = W1 vb + b1
        if (tid < SD)
            va[tid] = matvec100(at4s, vb4, tid)
                    + bwx * w[INW(k + 7) * 2] + bwy * w[INW(k + 7) * 2 + 1]
                    + u[INW(k + 7) * SD + tid] + db2;
        else if (tid >= 104 && tid < 112) {
            const int z = tid - 104;
            float s = b1z;
#pragma unroll 4
            for (int j = 0; j < SD; j++) s += W1sm[z * SD + j] * vb[j];
            g_Qq[(size_t)b * 32 + 16 + z] = s;
        }
        __syncthreads();
        // s7: q3 = W1 va + b1
        if (tid >= 104 && tid < 112) {
            const int z = tid - 104;
            float s = b1z;
#pragma unroll 4
            for (int j = 0; j < SD; j++) s += W1sm[z * SD + j] * va[j];
            g_Qq[(size_t)b * 32 + 24 + z] = s;
        }
        __syncthreads();
#undef INW
    }
}

// ============================================================================
// 3) serial: 16384 four-step blocks, 160 threads, ONE barrier/phase.
//    w0-2: c rows 0-95 (full 132-dot each). w3: chain (32 lanes, own SMSP).
//    w4: c rows 96-99, each split across 8 lanes + shfl_xor reduce.
// ============================================================================
__global__ void __launch_bounds__(160, 1) serial_kernel(const float* __restrict__ c0)
{
    __shared__ __align__(16) float sbuf[2][136];
    __shared__ float sC[3][8][32];

    const int tid = threadIdx.x;
    const int wid = tid >> 5;
    const int l   = tid & 31;
    const bool isG     = (wid < 3);
    const bool isChain = (wid == 3);
    const bool isW4    = (wid == 4);
    const int grp = l >> 3;          // w4: which of rows 96..99
    const int seg = l & 7;           // w4: segment
    const int ci  = l >> 3;          // chain group
    // sC tables: sC[s][j][lane] = V_{i-s-1}[z][j] (i>s), else 0
    for (int o = tid; o < 768; o += 160) {
        const int s = o >> 8, r = o & 255, j = r >> 5, lane = r & 31;
        const int i = lane >> 3, z = lane & 7;
        float v = 0.f;
        if (i > s) v = g_V[(i - s - 1) * 64 + z * HID + j];
        sC[s][j][lane] = v;
    }
    // init S_0 = [c0 | h1 | h2 | h3 | h4]
    if (tid < SD)        sbuf[0][tid] = c0[tid];
    else if (tid < SW)   sbuf[0][tid] = g_h[(size_t)(1 + ((tid - 100) >> 3)) * HID + ((tid - 100) & 7)];
    else if (tid < 136)  sbuf[0][tid] = 0.f;
    if (tid < 136) sbuf[1][tid] = 0.f;

    // rows
    unsigned long long rva[66];
    unsigned long long rw4[9];
    if (isG || isChain) {
        const float* Rr = g_R + (size_t)(isG ? tid : (100 + l)) * SW;
#pragma unroll
        for (int q = 0; q < 66; q++) rva[q] = pack2(Rr[2 * q], Rr[2 * q + 1]);
    } else {
        const float* Rr = g_R + (size_t)(96 + grp) * SW;
#pragma unroll
        for (int k = 0; k < 9; k++) {
            const int idx = seg + 8 * k;
            rw4[k] = (idx < 66) ? pack2(Rr[2 * idx], Rr[2 * idx + 1]) : 0ull;
        }
    }

    // in-chain coeff base addresses
    const unsigned aS = (unsigned)__cvta_generic_to_shared(&sC[0][0][l]);

    // prefetch (depth 2)
    const float* pPtr = 0;
    float pc = 0.f, pn = 0.f;
    if (isG) {
        pc = g_P4[tid]; pn = g_P4[SD + tid];
        pPtr = g_P4 + 2 * SD + tid;
    } else if (isChain) {
        pc = g_Qq[l]; pn = g_Qq[32 + l];
        pPtr = g_Qq + 2 * 32 + l;
    } else if (isW4 && seg == 0) {
        pc = g_P4[96 + grp]; pn = g_P4[SD + 96 + grp];
        pPtr = g_P4 + 2 * SD + 96 + grp;
    }
    float* gPtr = g_G + SD + (isG ? tid : (96 + grp));
    float* hPtr = g_h + (size_t)(5 + ci) * HID + (l & 7);

    __syncthreads();

    int p = 0;
    for (int b = 0; b < NB4; b++) {
        float pn2 = 0.f;
        if (pPtr) pn2 = __ldcg(pPtr);

        float dotv = 0.f;
        if (isG || isChain) {
            unsigned long long a0 = 0ull, a1 = 0ull, a2 = 0ull, a3 = 0ull;
            const ulonglong2* sp = reinterpret_cast<const ulonglong2*>(sbuf[p]);
#pragma unroll
            for (int q = 0; q < 33; q++) {
                ulonglong2 gg = sp[q];
                if (q & 1) { fma2(a2, rva[2 * q], gg.x); fma2(a3, rva[2 * q + 1], gg.y); }
                else       { fma2(a0, rva[2 * q], gg.x); fma2(a1, rva[2 * q + 1], gg.y); }
            }
            add2(a0, a1); add2(a2, a3); add2(a0, a2);
            float lo, hi; unpack2(a0, lo, hi);
            dotv = lo + hi;
        } else {
            // w4: split dot + butterfly reduce within 8-lane groups
            unsigned long long a0 = 0ull;
            const unsigned long long* sp = reinterpret_cast<const unsigned long long*>(sbuf[p]);
#pragma unroll
            for (int k = 0; k < 9; k++) {
                const int idx = seg + 8 * k;
                if (idx < 66) fma2(a0, rw4[k], sp[idx]);
            }
            float lo, hi; unpack2(a0, lo, hi);
            float v = lo + hi;
            v += __shfl_xor_sync(0xffffffffu, v, 1);
            v += __shfl_xor_sync(0xffffffffu, v, 2);
            v += __shfl_xor_sync(0xffffffffu, v, 4);
            dotv = v;
        }
        const int np = p ^ 1;

        if (isG) {
            const float gn = dotv + pc;
            sbuf[np][tid] = gn;
            *gPtr = gn; gPtr += SD;
        } else if (isW4) {
            if (seg == 0) {
                const float gn = dotv + pc;
                sbuf[np][96 + grp] = gn;
                *gPtr = gn;
            }
            gPtr += SD;
        } else {
            // chain: 3 coupling stages, all in warp 3
            float acc = dotv + pc;
            float val0 = tanh_hw(acc);
            float c[8];
#pragma unroll
            for (int j = 0; j < 8; j++)
                asm volatile("ld.shared.f32 %0, [%1];" : "=f"(c[j]) : "r"(aS + j * 128));
#pragma unroll
            for (int j = 0; j < 8; j++)
                acc = fmaf(c[j], __shfl_sync(0xffffffffu, val0, j), acc);
            float val1 = tanh_hw(acc);
#pragma unroll
            for (int j = 0; j < 8; j++)
                asm volatile("ld.shared.f32 %0, [%1];" : "=f"(c[j]) : "r"(aS + 1024 + j * 128));
#pragma unroll
            for (int j = 0; j < 8; j++)
                acc = fmaf(c[j], __shfl_sync(0xffffffffu, val1, 8 + j), acc);
            float val2 = tanh_hw(acc);
#pragma unroll
            for (int j = 0; j < 8; j++)
                asm volatile("ld.shared.f32 %0, [%1];" : "=f"(c[j]) : "r"(aS + 2048 + j * 128));
#pragma unroll
            for (int j = 0; j < 8; j++)
                acc = fmaf(c[j], __shfl_sync(0xffffffffu, val2, 16 + j), acc);
            float val3 = tanh_hw(acc);
            float hv = (l < 8) ? val0 : (l < 16) ? val1 : (l < 24) ? val2 : val3;
            sbuf[np][100 + l] = hv;
            *hPtr = hv; hPtr += 32;
        }

        pc = pn; pn = pn2;
        if (pPtr && b < NB4 - 3) pPtr += (isChain ? 32 : SD);
        __syncthreads();
        p = np;
    }
}

// ============================================================================
// 4) post: reconstruct c_{4m+1..3} from anchors + h; anchor m+1 row; y.
// ============================================================================
__global__ void __launch_bounds__(128, 1) post_kernel(
    const float* __restrict__ w, const float* __restrict__ u,
    const float* __restrict__ Bw, const float* __restrict__ W2,
    const float* __restrict__ b2, const int* __restrict__ obs,
    float* __restrict__ outc, float* __restrict__ outy)
{
    __shared__ __align__(16) float4 at4s[SD * 25];
    __shared__ __align__(16) float va[SD];
    __shared__ float hh[32];
    __shared__ int obsS[NOBS];

    const int tid = threadIdx.x;
    const float4* gAt4 = reinterpret_cast<const float4*>(g_At4);
    for (int o = tid; o < SD * 25; o += 128) at4s[o] = gAt4[o];
    if (tid < NOBS) obsS[tid] = obs[tid];

    float bwx = 0.f, bwy = 0.f, db2 = 0.f, w2r[HID];
#pragma unroll
    for (int z = 0; z < HID; z++) w2r[z] = 0.f;
    if (tid < SD) {
        bwx = Bw[tid * 2]; bwy = Bw[tid * 2 + 1]; db2 = DTC * b2[tid];
#pragma unroll
        for (int z = 0; z < HID; z++) w2r[z] = DTC * W2[tid * HID + z];
    }
    __syncthreads();

    const float4* va4 = reinterpret_cast<const float4*>(va);

    for (int gi = 0; gi < GQ; gi++) {
        const int m = blockIdx.x * GQ + gi;
        const int t0 = 4 * m;

        if (tid < 32) hh[tid] = g_h[(size_t)(t0 + 1 + (tid >> 3)) * HID + (tid & 7)];
        if (tid < SD) va[tid] = g_G[(size_t)m * SD + tid];
        __syncthreads();
#pragma unroll
        for (int s = 1; s <= 3; s++) {
            const int t = t0 + s;
            float cv = 0.f;
            if (tid < SD) {
                cv = matvec100(at4s, va4, tid)
                   + bwx * w[2 * (t - 1)] + bwy * w[2 * (t - 1) + 1]
                   + u[(size_t)(t - 1) * SD + tid] + db2;
#pragma unroll
                for (int z = 0; z < HID; z++) cv += w2r[z] * hh[8 * (s - 1) + z];
            }
            __syncthreads();
            if (tid < SD) {
                va[tid] = cv;
                outc[(size_t)(t - 1) * SD + tid] = cv;
            }
            __syncthreads();
            if (tid < NOBS) outy[(size_t)(t - 1) * NOBS + tid] = va[obsS[tid]];
        }
        // row t0+4 = anchor m+1
        __syncthreads();
        if (tid < SD) {
            float cv = g_G[(size_t)(m + 1) * SD + tid];
            va[tid] = cv;
            outc[(size_t)(t0 + 3) * SD + tid] = cv;
        }
        __syncthreads();
        if (tid < NOBS) outy[(size_t)(t0 + 3) * NOBS + tid] = va[obsS[tid]];
        __syncthreads();
    }
}

extern "C" void kernel_launch(void* const* d_in, const int* in_sizes, int n_in,
                              void* d_out, int out_size) {
    const float* c0  = (const float*)d_in[0];
    const float* w   = (const float*)d_in[1];
    const float* u   = (const float*)d_in[2];
    const float* A   = (const float*)d_in[3];
    const float* Bw  = (const float*)d_in[4];
    const float* W1  = (const float*)d_in[5];
    const float* b1  = (const float*)d_in[6];
    const float* W2  = (const float*)d_in[7];
    const float* b2  = (const float*)d_in[8];
    const int*   ob  = (const int*)d_in[9];

    float* outc = (float*)d_out;                      // (T, 100)
    float* outy = (float*)d_out + (size_t)TT * SD;    // (T, 12)

    setup1_kernel<<<1, 128>>>(A, Bw, W1, b1, W2, b2, c0, w, u);
    setup2_kernel<<<1, 128>>>(A, W1, W2);
    precomp_kernel<<<PRE_CTAS, 128>>>(w, u, Bw, W1, b1, b2);
    serial_kernel<<<1, 160>>>(c0);
    post_kernel<<<POST_CTAS, 128>>>(w, u, Bw, W2, b2, ob, outc, outy);
}

// round 10
// speedup vs baseline: 1.0177x; 1.0177x over previous
#include <cuda_runtime.h>

#define TT    65536
#define NB4   16384          /* 4*NB4 = 65536 serial 4-step blocks */
#define SD    100
#define HID   8
#define NOBS  12
#define DTC   0.01f
#define SW    132            /* state width */
#define GQ    8
#define PRE_CTAS  (NB4 / GQ) /* 2048, exact */
#define POST_CTAS (NB4 / GQ) /* 2048, exact */

__device__ __forceinline__ unsigned long long pack2(float lo, float hi) {
    unsigned long long r;
    asm("mov.b64 %0, {%1, %2};" : "=l"(r) : "f"(lo), "f"(hi));
    return r;
}
__device__ __forceinline__ void unpack2(unsigned long long v, float& lo, float& hi) {
    asm("mov.b64 {%0, %1}, %2;" : "=f"(lo), "=f"(hi) : "l"(v));
}
__device__ __forceinline__ void fma2(unsigned long long& acc, unsigned long long a, unsigned long long b) {
    asm("fma.rn.f32x2 %0, %1, %2, %0;" : "+l"(acc) : "l"(a), "l"(b));
}
__device__ __forceinline__ void add2(unsigned long long& acc, unsigned long long b) {
    asm("add.rn.f32x2 %0, %0, %1;" : "+l"(acc) : "l"(b));
}
__device__ __forceinline__ float tanh_hw(float x) {
    float r;
    asm("tanh.approx.f32 %0, %1;" : "=f"(r) : "f"(x));
    return r;
}

// ------------------------- device scratch -------------------------
__device__ float g_R[132 * SW];          // rows 0-99: c-rows; 100-131: chain rows
__device__ float g_At4[SD * SD];         // A in float4-interleaved matvec layout
__device__ float g_U1[SD * HID];         // dt A W2
__device__ float g_U2[SD * HID];         // dt A^2 W2
__device__ float g_V[7 * 64];            // V_j = dt W1 A^j W2, j=0..6
__device__ float g_P4[(size_t)NB4 * SD];
__device__ float g_Qq[(size_t)NB4 * 32]; // q0|q1|q2|q3 per block
__device__ float g_G[(size_t)(NB4 + 1) * SD];   // anchors c_{4b} (row 0 = c0)
__device__ float g_h[(size_t)(TT + 9) * HID];   // h_t rows

// ============================================================================
// 1a) setup1 (1 CTA): c-rows [A^4 | dtA^3W2 | dtA^2W2 | dtAW2 | dtW2],
//     At4 layout, initial rollout h1..h4, anchor row 0.
// ============================================================================
__global__ void __launch_bounds__(128, 1) setup1_kernel(
    const float* __restrict__ A,  const float* __restrict__ Bw,
    const float* __restrict__ W1, const float* __restrict__ b1,
    const float* __restrict__ W2, const float* __restrict__ b2,
    const float* __restrict__ c0, const float* __restrict__ w,
    const float* __restrict__ u)
{
    __shared__ float As[SD * SD];
    __shared__ float W2d[SD * HID];
    __shared__ float W1s[SD * HID];
    __shared__ float cva[SD];
    __shared__ float cvb[SD];
    __shared__ float hh[HID];

    const int tid = threadIdx.x;

    for (int i = tid; i < SD * SD; i += 128) As[i] = A[i];
    for (int i = tid; i < SD * HID; i += 128) W2d[i] = DTC * W2[i];
    for (int i = tid; i < SD * HID; i += 128) W1s[i] = W1[i];
    if (tid < SD) { cva[tid] = c0[tid]; g_G[tid] = c0[tid]; }
    __syncthreads();
    for (int o = tid; o < SD * SD; o += 128) {
        int j4 = o / 400, rem = o % 400, i = rem / 4, r = rem % 4;
        g_At4[o] = As[i * SD + 4 * j4 + r];
    }

    // initial rollout: h_t = tanh(W1 c_{t-1} + b1), c_t = A c_{t-1} + in_t + dtW2 h_t
    float* cc = cva; float* cn = cvb;
    for (int t = 1; t <= 4; t++) {
        if (tid >= 104 && tid < 112) {
            const int z = tid - 104;
            float s = b1[z];
            for (int k = 0; k < SD; k++) s += W1s[z * SD + k] * cc[k];
            float ht = tanh_hw(s);
            hh[z] = ht;
            g_h[(size_t)t * HID + z] = ht;
        }
        __syncthreads();
        if (t < 4 && tid < SD) {
            const int i = tid;
            float s = Bw[i * 2] * w[(t - 1) * 2] + Bw[i * 2 + 1] * w[(t - 1) * 2 + 1]
                    + u[(size_t)(t - 1) * SD + i] + DTC * b2[i];
            for (int j = 0; j < SD; j++) s += As[i * SD + j] * cc[j];
#pragma unroll
            for (int z = 0; z < HID; z++) s += W2d[i * HID + z] * hh[z];
            cn[i] = s;
        }
        __syncthreads();
        float* t2 = cc; cc = cn; cn = t2;
    }

    float ra[SD], rb[SD];
    float u1r[HID], u2r[HID];
    if (tid < SD) {
        const int i = tid;
#pragma unroll
        for (int jj = 0; jj < SD; jj++) ra[jj] = 0.f;
#pragma unroll
        for (int z = 0; z < HID; z++) u1r[z] = 0.f;
        for (int j = 0; j < SD; j++) {
            const float a = As[i * SD + j];
#pragma unroll
            for (int jj = 0; jj < SD; jj++) ra[jj] += a * As[j * SD + jj];
#pragma unroll
            for (int z = 0; z < HID; z++) u1r[z] += a * W2d[j * HID + z];
        }
#pragma unroll
        for (int z = 0; z < HID; z++) g_U1[i * HID + z] = u1r[z];
#pragma unroll
        for (int jj = 0; jj < SD; jj++) rb[jj] = 0.f;
        for (int j = 0; j < SD; j++) {
            const float a = ra[j];
#pragma unroll
            for (int jj = 0; jj < SD; jj++) rb[jj] += a * As[j * SD + jj];
        }
#pragma unroll
        for (int jj = 0; jj < SD; jj++) ra[jj] = 0.f;
        for (int j = 0; j < SD; j++) {
            const float a = rb[j];
#pragma unroll
            for (int jj = 0; jj < SD; jj++) ra[jj] += a * As[j * SD + jj];
        }
        for (int jj = 0; jj < SD; jj++) g_R[i * SW + jj] = ra[jj];
    }
    __syncthreads();
    for (int o = tid; o < SD * HID; o += 128) W1s[o] = g_U1[o];
    __syncthreads();
    if (tid < SD) {
        const int i = tid;
#pragma unroll
        for (int z = 0; z < HID; z++) u2r[z] = 0.f;
        for (int j = 0; j < SD; j++) {
            const float a = As[i * SD + j];
#pragma unroll
            for (int z = 0; z < HID; z++) u2r[z] += a * W1s[j * HID + z];
        }
#pragma unroll
        for (int z = 0; z < HID; z++) g_U2[i * HID + z] = u2r[z];
    }
    __syncthreads();
    for (int o = tid; o < SD * HID; o += 128) W1s[o] = g_U2[o];
    __syncthreads();
    if (tid < SD) {
        const int i = tid;
        float u3r[HID];
#pragma unroll
        for (int z = 0; z < HID; z++) u3r[z] = 0.f;
        for (int j = 0; j < SD; j++) {
            const float a = As[i * SD + j];
#pragma unroll
            for (int z = 0; z < HID; z++) u3r[z] += a * W1s[j * HID + z];
        }
#pragma unroll
        for (int z = 0; z < HID; z++) {
            g_R[i * SW + 100 + z] = u3r[z];
            g_R[i * SW + 108 + z] = u2r[z];
            g_R[i * SW + 116 + z] = u1r[z];
            g_R[i * SW + 124 + z] = W2d[i * HID + z];
        }
    }
}

// ============================================================================
// 1b) setup2 (1 CTA): chain rows (W1A^{4+i} heads, V tails) + V tables.
// ============================================================================
__global__ void __launch_bounds__(128, 1) setup2_kernel(
    const float* __restrict__ A, const float* __restrict__ W1,
    const float* __restrict__ W2)
{
    __shared__ float As[SD * SD];
    __shared__ float bufA[SD * HID];
    __shared__ float bufB[SD * HID];

    const int tid = threadIdx.x;
    for (int i = tid; i < SD * SD; i += 128) As[i] = A[i];
    for (int i = tid; i < SD * HID; i += 128) bufA[i] = W1[i];
    __syncthreads();

    float* cur = bufA;
    float* nxt = bufB;

    for (int o = tid; o < 64; o += 128) {
        const int z = o >> 3, zz = o & 7;
        float s = 0.f;
        for (int j = 0; j < SD; j++) s += cur[z * SD + j] * (DTC * W2[j * HID + zz]);
        g_V[o] = s;
    }
    __syncthreads();

    for (int k = 1; k <= 7; k++) {
        for (int o = tid; o < SD * HID; o += 128) {
            const int z = o / SD, jj = o % SD;
            float s = 0.f;
            for (int j = 0; j < SD; j++) s += cur[z * SD + j] * As[j * SD + jj];
            nxt[o] = s;
        }
        __syncthreads();
        float* t = cur; cur = nxt; nxt = t;
        if (k >= 4) {
            for (int o = tid; o < SD * HID; o += 128) {
                const int z = o / SD, jj = o % SD;
                g_R[(size_t)(100 + 8 * (k - 4) + z) * SW + jj] = cur[o];
            }
        }
        if (k <= 6) {
            for (int o = tid; o < 64; o += 128) {
                const int z = o >> 3, zz = o & 7;
                float s = 0.f;
                for (int j = 0; j < SD; j++) s += cur[z * SD + j] * (DTC * W2[j * HID + zz]);
                g_V[k * 64 + o] = s;
            }
        }
        __syncthreads();
    }

    for (int o = tid; o < 32 * 32; o += 128) {
        const int l = o >> 5, cidx = o & 31;
        const int m = cidx >> 3, zz = cidx & 7;
        const int i = l >> 3, z = l & 7;
        const int d = 3 + i - m;
        g_R[(size_t)(100 + l) * SW + 100 + cidx] = g_V[d * 64 + z * HID + zz];
    }
}

__device__ __forceinline__ float matvec100(const float4* at4s, const float4* v4, int i) {
    float acc = 0.f;
#pragma unroll
    for (int j4 = 0; j4 < 25; j4++) {
        float4 m = at4s[j4 * SD + i];
        float4 x = v4[j4];
        acc = fmaf(m.x, x.x, acc); acc = fmaf(m.y, x.y, acc);
        acc = fmaf(m.z, x.z, acc); acc = fmaf(m.w, x.w, acc);
    }
    return acc;
}

// ============================================================================
// 2) precomp: P_b and q0..q3 per 4-step block
// ============================================================================
__global__ void __launch_bounds__(128, 1) precomp_kernel(
    const float* __restrict__ w, const float* __restrict__ u,
    const float* __restrict__ Bw, const float* __restrict__ W1,
    const float* __restrict__ b1, const float* __restrict__ b2)
{
    __shared__ __align__(16) float4 at4s[SD * 25];
    __shared__ float W1sm[SD * HID];
    __shared__ __align__(16) float va[SD];
    __shared__ __align__(16) float vb[SD];

    const int tid = threadIdx.x;
    const float4* gAt4 = reinterpret_cast<const float4*>(g_At4);
    for (int o = tid; o < SD * 25; o += 128) at4s[o] = gAt4[o];
    for (int o = tid; o < SD * HID; o += 128) W1sm[o] = W1[o];

    float bwx = 0.f, bwy = 0.f, db2 = 0.f;
    if (tid < SD) { bwx = Bw[tid * 2]; bwy = Bw[tid * 2 + 1]; db2 = DTC * b2[tid]; }
    float b1z = 0.f;
    if (tid >= 104 && tid < 112) b1z = b1[tid - 104];
    __syncthreads();

    const float4* va4 = reinterpret_cast<const float4*>(va);
    const float4* vb4 = reinterpret_cast<const float4*>(vb);

    for (int gi = 0; gi < GQ; gi++) {
        const int b = blockIdx.x * GQ + gi;
        const size_t k = 4 * (size_t)b;

#define INW(t)  ((size_t)(((t) <= TT ? (t) : TT) - 1))
        if (tid < SD)
            va[tid] = bwx * w[INW(k + 1) * 2] + bwy * w[INW(k + 1) * 2 + 1]
                    + u[INW(k + 1) * SD + tid] + db2;
        __syncthreads();
        if (tid < SD)
            vb[tid] = matvec100(at4s, va4, tid)
                    + bwx * w[INW(k + 2) * 2] + bwy * w[INW(k + 2) * 2 + 1]
                    + u[INW(k + 2) * SD + tid] + db2;
        __syncthreads();
        if (tid < SD)
            va[tid] = matvec100(at4s, vb4, tid)
                    + bwx * w[INW(k + 3) * 2] + bwy * w[INW(k + 3) * 2 + 1]
                    + u[INW(k + 3) * SD + tid] + db2;
        __syncthreads();
        if (tid < SD)
            vb[tid] = matvec100(at4s, va4, tid)
                    + bwx * w[INW(k + 4) * 2] + bwy * w[INW(k + 4) * 2 + 1]
                    + u[INW(k + 4) * SD + tid] + db2;
        __syncthreads();
        if (tid < SD) {
            g_P4[(size_t)b * SD + tid] = vb[tid];
            va[tid] = matvec100(at4s, vb4, tid)
                    + bwx * w[INW(k + 5) * 2] + bwy * w[INW(k + 5) * 2 + 1]
                    + u[INW(k + 5) * SD + tid] + db2;
        } else if (tid >= 104 && tid < 112) {
            const int z = tid - 104;
            float s = b1z;
#pragma unroll 4
            for (int j = 0; j < SD; j++) s += W1sm[z * SD + j] * vb[j];
            g_Qq[(size_t)b * 32 + z] = s;
        }
        __syncthreads();
        if (tid < SD)
            vb[tid] = matvec100(at4s, va4, tid)
                    + bwx * w[INW(k + 6) * 2] + bwy * w[INW(k + 6) * 2 + 1]
                    + u[INW(k + 6) * SD + tid] + db2;
        else if (tid >= 104 && tid < 112) {
            const int z = tid - 104;
            float s = b1z;
#pragma unroll 4
            for (int j = 0; j < SD; j++) s += W1sm[z * SD + j] * va[j];
            g_Qq[(size_t)b * 32 + 8 + z] = s;
        }
        __syncthreads();
        if (tid < SD)
            va[tid] = matvec100(at4s, vb4, tid)
                    + bwx * w[INW(k + 7) * 2] + bwy * w[INW(k + 7) * 2 + 1]
                    + u[INW(k + 7) * SD + tid] + db2;
        else if (tid >= 104 && tid < 112) {
            const int z = tid - 104;
            float s = b1z;
#pragma unroll 4
            for (int j = 0; j < SD; j++) s += W1sm[z * SD + j] * vb[j];
            g_Qq[(size_t)b * 32 + 16 + z] = s;
        }
        __syncthreads();
        if (tid >= 104 && tid < 112) {
            const int z = tid - 104;
            float s = b1z;
#pragma unroll 4
            for (int j = 0; j < SD; j++) s += W1sm[z * SD + j] * va[j];
            g_Qq[(size_t)b * 32 + 24 + z] = s;
        }
        __syncthreads();
#undef INW
    }
}

// ============================================================================
// 3) serial: 16384 four-step phases, 192 threads, software-pipelined dots.
//    w0-2: c rows 0-95.  w3: chain (own SMSP).  w4: rows 96-99 split 8-way.
//    w5: c-part partials of the 32 chain rows (computed one phase ahead).
//    Per phase: finish h-part -> bar1(160, no chain) -> shadow c-part -> bar all.
// ============================================================================
__global__ void __launch_bounds__(192, 1) serial_kernel(const float* __restrict__ c0)
{
    __shared__ __align__(16) float sbuf[2][136];
    __shared__ float sPart[2][32];

    const int tid = threadIdx.x;
    const int wid = tid >> 5;
    const int l   = tid & 31;
    const bool isG     = (wid < 3);
    const bool isChain = (wid == 3);
    const bool isW4    = (wid == 4);
    const bool isP5    = (wid == 5);
    const int grp = l >> 3;
    const int seg = l & 7;

    // init S_0 = [c0 | h1 | h2 | h3 | h4]
    if (tid < SD)       sbuf[0][tid] = c0[tid];
    else if (tid < SW)  sbuf[0][tid] = g_h[(size_t)(1 + ((tid - 100) >> 3)) * HID + ((tid - 100) & 7)];
    else if (tid < 136) sbuf[0][tid] = 0.f;
    if (tid < 136) sbuf[1][tid] = 0.f;
    if (tid < 32) { sPart[0][tid] = 0.f; sPart[1][tid] = 0.f; }

    // weight overlay: all roles share rva[66] (union stays 132 regs)
    unsigned long long rva[66];
#pragma unroll
    for (int q = 0; q < 66; q++) rva[q] = 0ull;
    float cp0[8], cp1[8], cp2[8];
#pragma unroll
    for (int j = 0; j < 8; j++) { cp0[j] = 0.f; cp1[j] = 0.f; cp2[j] = 0.f; }

    if (isG) {
        const float* Rr = g_R + (size_t)tid * SW;
#pragma unroll
        for (int q = 0; q < 66; q++) rva[q] = pack2(Rr[2 * q], Rr[2 * q + 1]);
    } else if (isChain) {
        const float* Rr = g_R + (size_t)(100 + l) * SW;
#pragma unroll
        for (int q = 0; q < 16; q++) rva[q] = pack2(Rr[100 + 2 * q], Rr[100 + 2 * q + 1]);
        const int ii = l >> 3, z = l & 7;
#pragma unroll
        for (int j = 0; j < 8; j++) {
            cp0[j] = (ii > 0) ? g_V[(ii - 1) * 64 + z * HID + j] : 0.f;
            cp1[j] = (ii > 1) ? g_V[(ii - 2) * 64 + z * HID + j] : 0.f;
            cp2[j] = (ii > 2) ? g_V[(ii - 3) * 64 + z * HID + j] : 0.f;
        }
    } else if (isP5) {
        const float* Rr = g_R + (size_t)(100 + l) * SW;
#pragma unroll
        for (int q = 0; q < 50; q++) rva[q] = pack2(Rr[2 * q], Rr[2 * q + 1]);
    } else if (isW4) {
        const float* Rr = g_R + (size_t)(96 + grp) * SW;
#pragma unroll
        for (int k = 0; k < 9; k++) {
            const int idx = seg + 8 * k;
            if (idx < 66) rva[k] = pack2(Rr[2 * idx], Rr[2 * idx + 1]);
        }
    }

    // prefetch (depth 2)
    const float* pPtr = 0;
    float pc = 0.f, pn = 0.f;
    if (isG) {
        pc = g_P4[tid]; pn = g_P4[SD + tid];
        pPtr = g_P4 + 2 * SD + tid;
    } else if (isChain) {
        pc = g_Qq[l]; pn = g_Qq[32 + l];
        pPtr = g_Qq + 2 * 32 + l;
    } else if (isW4 && seg == 0) {
        pc = g_P4[96 + grp]; pn = g_P4[SD + 96 + grp];
        pPtr = g_P4 + 2 * SD + 96 + grp;
    }
    float* gPtr = g_G + SD + (isG ? tid : (96 + grp));
    float* hPtr = g_h + (size_t)(5 + grp) * HID + seg;

    __syncthreads();   // sbuf[0] visible

    // pre-loop shadow vs sbuf[0]
    unsigned long long a0 = 0ull, a1 = 0ull, a2 = 0ull, a3 = 0ull;
    {
        const ulonglong2* sq = reinterpret_cast<const ulonglong2*>(sbuf[0]);
        if (isG) {
#pragma unroll
            for (int q = 0; q < 25; q++) {
                ulonglong2 gg = sq[q];
                if (q & 1) { fma2(a2, rva[2 * q], gg.x); fma2(a3, rva[2 * q + 1], gg.y); }
                else       { fma2(a0, rva[2 * q], gg.x); fma2(a1, rva[2 * q + 1], gg.y); }
            }
        } else if (isP5) {
            unsigned long long b0 = 0ull, b1 = 0ull, b2 = 0ull, b3 = 0ull;
#pragma unroll
            for (int q = 0; q < 25; q++) {
                ulonglong2 gg = sq[q];
                if (q & 1) { fma2(b2, rva[2 * q], gg.x); fma2(b3, rva[2 * q + 1], gg.y); }
                else       { fma2(b0, rva[2 * q], gg.x); fma2(b1, rva[2 * q + 1], gg.y); }
            }
            add2(b0, b1); add2(b2, b3); add2(b0, b2);
            float lo, hi; unpack2(b0, lo, hi);
            sPart[0][l] = lo + hi;
        } else if (isW4) {
            const unsigned long long* s1 = reinterpret_cast<const unsigned long long*>(sbuf[0]);
#pragma unroll
            for (int k = 0; k < 9; k++) {
                const int idx = seg + 8 * k;
                if (idx < 50) fma2(a0, rva[k], s1[idx]);
            }
        }
    }
    __syncthreads();   // sPart[0] visible to chain

    int p = 0;
    for (int b = 0; b < NB4; b++) {
        float pn2 = 0.f;
        if (pPtr) pn2 = __ldcg(pPtr);
        const int np = p ^ 1;

        if (isG) {
            // finish: h-part vs sbuf[p]
            const ulonglong2* sp = reinterpret_cast<const ulonglong2*>(sbuf[p]);
#pragma unroll
            for (int q = 25; q < 33; q++) {
                ulonglong2 gg = sp[q];
                if (q & 1) { fma2(a2, rva[2 * q], gg.x); fma2(a3, rva[2 * q + 1], gg.y); }
                else       { fma2(a0, rva[2 * q], gg.x); fma2(a1, rva[2 * q + 1], gg.y); }
            }
            add2(a0, a1); add2(a2, a3); add2(a0, a2);
            float lo, hi; unpack2(a0, lo, hi);
            const float gn = lo + hi + pc;
            sbuf[np][tid] = gn;
            *gPtr = gn; gPtr += SD;
            asm volatile("bar.sync 1, 160;" ::: "memory");
            // shadow: c-part for next phase vs sbuf[np]
            a0 = 0ull; a1 = 0ull; a2 = 0ull; a3 = 0ull;
            const ulonglong2* sq = reinterpret_cast<const ulonglong2*>(sbuf[np]);
#pragma unroll
            for (int q = 0; q < 25; q++) {
                ulonglong2 gg = sq[q];
                if (q & 1) { fma2(a2, rva[2 * q], gg.x); fma2(a3, rva[2 * q + 1], gg.y); }
                else       { fma2(a0, rva[2 * q], gg.x); fma2(a1, rva[2 * q + 1], gg.y); }
            }
        } else if (isChain) {
            const float part = sPart[p][l];
            unsigned long long b0 = 0ull, b1 = 0ull;
            const ulonglong2* sp = reinterpret_cast<const ulonglong2*>(sbuf[p]);
#pragma unroll
            for (int m = 0; m < 8; m++) {
                ulonglong2 gg = sp[25 + m];
                fma2(b0, rva[2 * m], gg.x); fma2(b1, rva[2 * m + 1], gg.y);
            }
            add2(b0, b1);
            float lo, hi; unpack2(b0, lo, hi);
            float acc = part + lo + hi + pc;
            const float val0 = tanh_hw(acc);
            {
                float t0 = cp0[0] * __shfl_sync(0xffffffffu, val0, 0);
                float t1 = cp0[1] * __shfl_sync(0xffffffffu, val0, 1);
                float t2 = cp0[2] * __shfl_sync(0xffffffffu, val0, 2);
                float t3 = cp0[3] * __shfl_sync(0xffffffffu, val0, 3);
                float t4 = cp0[4] * __shfl_sync(0xffffffffu, val0, 4);
                float t5 = cp0[5] * __shfl_sync(0xffffffffu, val0, 5);
                float t6 = cp0[6] * __shfl_sync(0xffffffffu, val0, 6);
                float t7 = cp0[7] * __shfl_sync(0xffffffffu, val0, 7);
                acc += ((t0 + t1) + (t2 + t3)) + ((t4 + t5) + (t6 + t7));
            }
            const float val1 = tanh_hw(acc);
            {
                float t0 = cp1[0] * __shfl_sync(0xffffffffu, val1, 8);
                float t1 = cp1[1] * __shfl_sync(0xffffffffu, val1, 9);
                float t2 = cp1[2] * __shfl_sync(0xffffffffu, val1, 10);
                float t3 = cp1[3] * __shfl_sync(0xffffffffu, val1, 11);
                float t4 = cp1[4] * __shfl_sync(0xffffffffu, val1, 12);
                float t5 = cp1[5] * __shfl_sync(0xffffffffu, val1, 13);
                float t6 = cp1[6] * __shfl_sync(0xffffffffu, val1, 14);
                float t7 = cp1[7] * __shfl_sync(0xffffffffu, val1, 15);
                acc += ((t0 + t1) + (t2 + t3)) + ((t4 + t5) + (t6 + t7));
            }
            const float val2 = tanh_hw(acc);
            {
                float t0 = cp2[0] * __shfl_sync(0xffffffffu, val2, 16);
                float t1 = cp2[1] * __shfl_sync(0xffffffffu, val2, 17);
                float t2 = cp2[2] * __shfl_sync(0xffffffffu, val2, 18);
                float t3 = cp2[3] * __shfl_sync(0xffffffffu, val2, 19);
                float t4 = cp2[4] * __shfl_sync(0xffffffffu, val2, 20);
                float t5 = cp2[5] * __shfl_sync(0xffffffffu, val2, 21);
                float t6 = cp2[6] * __shfl_sync(0xffffffffu, val2, 22);
                float t7 = cp2[7] * __shfl_sync(0xffffffffu, val2, 23);
                acc += ((t0 + t1) + (t2 + t3)) + ((t4 + t5) + (t6 + t7));
            }
            const float val3 = tanh_hw(acc);
            const float hv = (l < 8) ? val0 : (l < 16) ? val1 : (l < 24) ? val2 : val3;
            sbuf[np][100 + l] = hv;
            *hPtr = hv; hPtr += 32;
            // chain does NOT join bar1
        } else if (isW4) {
            const unsigned long long* s1 = reinterpret_cast<const unsigned long long*>(sbuf[p]);
#pragma unroll
            for (int k = 0; k < 9; k++) {
                const int idx = seg + 8 * k;
                if (idx >= 50 && idx < 66) fma2(a0, rva[k], s1[idx]);
            }
            float lo, hi; unpack2(a0, lo, hi);
            float v = lo + hi;
            v += __shfl_xor_sync(0xffffffffu, v, 1);
            v += __shfl_xor_sync(0xffffffffu, v, 2);
            v += __shfl_xor_sync(0xffffffffu, v, 4);
            if (seg == 0) {
                const float gn = v + pc;
                sbuf[np][96 + grp] = gn;
                *gPtr = gn;
            }
            gPtr += SD;
            asm volatile("bar.sync 1, 160;" ::: "memory");
            a0 = 0ull;
            const unsigned long long* s2 = reinterpret_cast<const unsigned long long*>(sbuf[np]);
#pragma unroll
            for (int k = 0; k < 9; k++) {
                const int idx = seg + 8 * k;
                if (idx < 50) fma2(a0, rva[k], s2[idx]);
            }
        } else { // isP5
            asm volatile("bar.sync 1, 160;" ::: "memory");
            unsigned long long b0 = 0ull, b1 = 0ull, b2 = 0ull, b3 = 0ull;
            const ulonglong2* sq = reinterpret_cast<const ulonglong2*>(sbuf[np]);
#pragma unroll
            for (int q = 0; q < 25; q++) {
                ulonglong2 gg = sq[q];
                if (q & 1) { fma2(b2, rva[2 * q], gg.x); fma2(b3, rva[2 * q + 1], gg.y); }
                else       { fma2(b0, rva[2 * q], gg.x); fma2(b1, rva[2 * q + 1], gg.y); }
            }
            add2(b0, b1); add2(b2, b3); add2(b0, b2);
            float lo, hi; unpack2(b0, lo, hi);
            sPart[np][l] = lo + hi;
        }

        pc = pn; pn = pn2;
        if (pPtr && b < NB4 - 3) pPtr += (isChain ? 32 : SD);
        __syncthreads();
        p = np;
    }
}

// ============================================================================
// 4) post: reconstruct c_{4m+1..3} from anchors + h; anchor m+1 row; y.
// ============================================================================
__global__ void __launch_bounds__(128, 1) post_kernel(
    const float* __restrict__ w, const float* __restrict__ u,
    const float* __restrict__ Bw, const float* __restrict__ W2,
    const float* __restrict__ b2, const int* __restrict__ obs,
    float* __restrict__ outc, float* __restrict__ outy)
{
    __shared__ __align__(16) float4 at4s[SD * 25];
    __shared__ __align__(16) float va[SD];
    __shared__ float hh[32];
    __shared__ int obsS[NOBS];

    const int tid = threadIdx.x;
    const float4* gAt4 = reinterpret_cast<const float4*>(g_At4);
    for (int o = tid; o < SD * 25; o += 128) at4s[o] = gAt4[o];
    if (tid < NOBS) obsS[tid] = obs[tid];

    float bwx = 0.f, bwy = 0.f, db2 = 0.f, w2r[HID];
#pragma unroll
    for (int z = 0; z < HID; z++) w2r[z] = 0.f;
    if (tid < SD) {
        bwx = Bw[tid * 2]; bwy = Bw[tid * 2 + 1]; db2 = DTC * b2[tid];
#pragma unroll
        for (int z = 0; z < HID; z++) w2r[z] = DTC * W2[tid * HID + z];
    }
    __syncthreads();

    const float4* va4 = reinterpret_cast<const float4*>(va);

    for (int gi = 0; gi < GQ; gi++) {
        const int m = blockIdx.x * GQ + gi;
        const int t0 = 4 * m;

        if (tid < 32) hh[tid] = g_h[(size_t)(t0 + 1 + (tid >> 3)) * HID + (tid & 7)];
        if (tid < SD) va[tid] = g_G[(size_t)m * SD + tid];
        __syncthreads();
#pragma unroll
        for (int s = 1; s <= 3; s++) {
            const int t = t0 + s;
            float cv = 0.f;
            if (tid < SD) {
                cv = matvec100(at4s, va4, tid)
                   + bwx * w[2 * (t - 1)] + bwy * w[2 * (t - 1) + 1]
                   + u[(size_t)(t - 1) * SD + tid] + db2;
#pragma unroll
                for (int z = 0; z < HID; z++) cv += w2r[z] * hh[8 * (s - 1) + z];
            }
            __syncthreads();
            if (tid < SD) {
                va[tid] = cv;
                outc[(size_t)(t - 1) * SD + tid] = cv;
            }
            __syncthreads();
            if (tid < NOBS) outy[(size_t)(t - 1) * NOBS + tid] = va[obsS[tid]];
        }
        __syncthreads();
        if (tid < SD) {
            float cv = g_G[(size_t)(m + 1) * SD + tid];
            va[tid] = cv;
            outc[(size_t)(t0 + 3) * SD + tid] = cv;
        }
        __syncthreads();
        if (tid < NOBS) outy[(size_t)(t0 + 3) * NOBS + tid] = va[obsS[tid]];
        __syncthreads();
    }
}

extern "C" void kernel_launch(void* const* d_in, const int* in_sizes, int n_in,
                              void* d_out, int out_size) {
    const float* c0  = (const float*)d_in[0];
    const float* w   = (const float*)d_in[1];
    const float* u   = (const float*)d_in[2];
    const float* A   = (const float*)d_in[3];
    const float* Bw  = (const float*)d_in[4];
    const float* W1  = (const float*)d_in[5];
    const float* b1  = (const float*)d_in[6];
    const float* W2  = (const float*)d_in[7];
    const float* b2  = (const float*)d_in[8];
    const int*   ob  = (const int*)d_in[9];

    float* outc = (float*)d_out;                      // (T, 100)
    float* outy = (float*)d_out + (size_t)TT * SD;    // (T, 12)

    setup1_kernel<<<1, 128>>>(A, Bw, W1, b1, W2, b2, c0, w, u);
    setup2_kernel<<<1, 128>>>(A, W1, W2);
    precomp_kernel<<<PRE_CTAS, 128>>>(w, u, Bw, W1, b1, b2);
    serial_kernel<<<1, 192>>>(c0);
    post_kernel<<<POST_CTAS, 128>>>(w, u, Bw, W2, b2, ob, outc, outy);
}

// round 13
// speedup vs baseline: 1.1371x; 1.1173x over previous
#include <cuda_runtime.h>

#define TT    65536
#define NB4   16384          /* 4*NB4 = 65536 serial 4-step blocks */
#define SD    100
#define HID   8
#define NOBS  12
#define DTC   0.01f
#define SW    132            /* state width */
#define GQ    8
#define PRE_CTAS  (NB4 / GQ) /* 2048, exact */
#define POST_CTAS (NB4 / GQ) /* 2048, exact */

__device__ __forceinline__ unsigned long long pack2(float lo, float hi) {
    unsigned long long r;
    asm("mov.b64 %0, {%1, %2};" : "=l"(r) : "f"(lo), "f"(hi));
    return r;
}
__device__ __forceinline__ void unpack2(unsigned long long v, float& lo, float& hi) {
    asm("mov.b64 {%0, %1}, %2;" : "=f"(lo), "=f"(hi) : "l"(v));
}
__device__ __forceinline__ void fma2(unsigned long long& acc, unsigned long long a, unsigned long long b) {
    asm("fma.rn.f32x2 %0, %1, %2, %0;" : "+l"(acc) : "l"(a), "l"(b));
}
__device__ __forceinline__ void add2(unsigned long long& acc, unsigned long long b) {
    asm("add.rn.f32x2 %0, %0, %1;" : "+l"(acc) : "l"(b));
}
__device__ __forceinline__ float tanh_hw(float x) {
    float r;
    asm("tanh.approx.f32 %0, %1;" : "=f"(r) : "f"(x));
    return r;
}

// ------------------------- device scratch -------------------------
__device__ float g_R[132 * SW];          // rows 0-99: c-rows; 100-131: chain rows
__device__ float g_At4[SD * SD];         // A in float4-interleaved matvec layout
__device__ float g_U1[SD * HID];         // dt A W2
__device__ float g_U2[SD * HID];         // dt A^2 W2
__device__ float g_V[7 * 64];            // V_j = dt W1 A^j W2, j=0..6
__device__ float g_P4[(size_t)NB4 * SD];
__device__ float g_Qq[(size_t)NB4 * 32]; // q0|q1|q2|q3 per block
__device__ float g_G[(size_t)(NB4 + 1) * SD];   // anchors c_{4b} (row 0 = c0)
__device__ float g_h[(size_t)(TT + 9) * HID];   // h_t rows

// ============================================================================
// 1a) setup1 (1 CTA): c-rows [A^4 | dtA^3W2 | dtA^2W2 | dtAW2 | dtW2],
//     At4 layout, initial rollout h1..h4, anchor row 0.
// ============================================================================
__global__ void __launch_bounds__(128, 1) setup1_kernel(
    const float* __restrict__ A,  const float* __restrict__ Bw,
    const float* __restrict__ W1, const float* __restrict__ b1,
    const float* __restrict__ W2, const float* __restrict__ b2,
    const float* __restrict__ c0, const float* __restrict__ w,
    const float* __restrict__ u)
{
    __shared__ float As[SD * SD];
    __shared__ float W2d[SD * HID];
    __shared__ float W1s[SD * HID];
    __shared__ float cva[SD];
    __shared__ float cvb[SD];
    __shared__ float hh[HID];

    const int tid = threadIdx.x;

    for (int i = tid; i < SD * SD; i += 128) As[i] = A[i];
    for (int i = tid; i < SD * HID; i += 128) W2d[i] = DTC * W2[i];
    for (int i = tid; i < SD * HID; i += 128) W1s[i] = W1[i];
    if (tid < SD) { cva[tid] = c0[tid]; g_G[tid] = c0[tid]; }
    __syncthreads();
    for (int o = tid; o < SD * SD; o += 128) {
        int j4 = o / 400, rem = o % 400, i = rem / 4, r = rem % 4;
        g_At4[o] = As[i * SD + 4 * j4 + r];
    }

    // initial rollout: h_t = tanh(W1 c_{t-1} + b1), c_t = A c_{t-1} + in_t + dtW2 h_t
    float* cc = cva; float* cn = cvb;
    for (int t = 1; t <= 4; t++) {
        if (tid >= 104 && tid < 112) {
            const int z = tid - 104;
            float s = b1[z];
            for (int k = 0; k < SD; k++) s += W1s[z * SD + k] * cc[k];
            float ht = tanh_hw(s);
            hh[z] = ht;
            g_h[(size_t)t * HID + z] = ht;
        }
        __syncthreads();
        if (t < 4 && tid < SD) {
            const int i = tid;
            float s = Bw[i * 2] * w[(t - 1) * 2] + Bw[i * 2 + 1] * w[(t - 1) * 2 + 1]
                    + u[(size_t)(t - 1) * SD + i] + DTC * b2[i];
            for (int j = 0; j < SD; j++) s += As[i * SD + j] * cc[j];
#pragma unroll
            for (int z = 0; z < HID; z++) s += W2d[i * HID + z] * hh[z];
            cn[i] = s;
        }
        __syncthreads();
        float* t2 = cc; cc = cn; cn = t2;
    }

    float ra[SD], rb[SD];
    float u1r[HID], u2r[HID];
    if (tid < SD) {
        const int i = tid;
#pragma unroll
        for (int jj = 0; jj < SD; jj++) ra[jj] = 0.f;
#pragma unroll
        for (int z = 0; z < HID; z++) u1r[z] = 0.f;
        for (int j = 0; j < SD; j++) {
            const float a = As[i * SD + j];
#pragma unroll
            for (int jj = 0; jj < SD; jj++) ra[jj] += a * As[j * SD + jj];
#pragma unroll
            for (int z = 0; z < HID; z++) u1r[z] += a * W2d[j * HID + z];
        }
#pragma unroll
        for (int z = 0; z < HID; z++) g_U1[i * HID + z] = u1r[z];
#pragma unroll
        for (int jj = 0; jj < SD; jj++) rb[jj] = 0.f;
        for (int j = 0; j < SD; j++) {
            const float a = ra[j];
#pragma unroll
            for (int jj = 0; jj < SD; jj++) rb[jj] += a * As[j * SD + jj];
        }
#pragma unroll
        for (int jj = 0; jj < SD; jj++) ra[jj] = 0.f;
        for (int j = 0; j < SD; j++) {
            const float a = rb[j];
#pragma unroll
            for (int jj = 0; jj < SD; jj++) ra[jj] += a * As[j * SD + jj];
        }
        for (int jj = 0; jj < SD; jj++) g_R[i * SW + jj] = ra[jj];
    }
    __syncthreads();
    for (int o = tid; o < SD * HID; o += 128) W1s[o] = g_U1[o];
    __syncthreads();
    if (tid < SD) {
        const int i = tid;
#pragma unroll
        for (int z = 0; z < HID; z++) u2r[z] = 0.f;
        for (int j = 0; j < SD; j++) {
            const float a = As[i * SD + j];
#pragma unroll
            for (int z = 0; z < HID; z++) u2r[z] += a * W1s[j * HID + z];
        }
#pragma unroll
        for (int z = 0; z < HID; z++) g_U2[i * HID + z] = u2r[z];
    }
    __syncthreads();
    for (int o = tid; o < SD * HID; o += 128) W1s[o] = g_U2[o];
    __syncthreads();
    if (tid < SD) {
        const int i = tid;
        float u3r[HID];
#pragma unroll
        for (int z = 0; z < HID; z++) u3r[z] = 0.f;
        for (int j = 0; j < SD; j++) {
            const float a = As[i * SD + j];
#pragma unroll
            for (int z = 0; z < HID; z++) u3r[z] += a * W1s[j * HID + z];
        }
#pragma unroll
        for (int z = 0; z < HID; z++) {
            g_R[i * SW + 100 + z] = u3r[z];
            g_R[i * SW + 108 + z] = u2r[z];
            g_R[i * SW + 116 + z] = u1r[z];
            g_R[i * SW + 124 + z] = W2d[i * HID + z];
        }
    }
}

// ============================================================================
// 1b) setup2 (1 CTA): chain rows (W1A^{4+i} heads, V tails) + V tables.
// ============================================================================
__global__ void __launch_bounds__(128, 1) setup2_kernel(
    const float* __restrict__ A, const float* __restrict__ W1,
    const float* __restrict__ W2)
{
    __shared__ float As[SD * SD];
    __shared__ float bufA[SD * HID];
    __shared__ float bufB[SD * HID];

    const int tid = threadIdx.x;
    for (int i = tid; i < SD * SD; i += 128) As[i] = A[i];
    for (int i = tid; i < SD * HID; i += 128) bufA[i] = W1[i];
    __syncthreads();

    float* cur = bufA;
    float* nxt = bufB;

    for (int o = tid; o < 64; o += 128) {
        const int z = o >> 3, zz = o & 7;
        float s = 0.f;
        for (int j = 0; j < SD; j++) s += cur[z * SD + j] * (DTC * W2[j * HID + zz]);
        g_V[o] = s;
    }
    __syncthreads();

    for (int k = 1; k <= 7; k++) {
        for (int o = tid; o < SD * HID; o += 128) {
            const int z = o / SD, jj = o % SD;
            float s = 0.f;
            for (int j = 0; j < SD; j++) s += cur[z * SD + j] * As[j * SD + jj];
            nxt[o] = s;
        }
        __syncthreads();
        float* t = cur; cur = nxt; nxt = t;
        if (k >= 4) {
            for (int o = tid; o < SD * HID; o += 128) {
                const int z = o / SD, jj = o % SD;
                g_R[(size_t)(100 + 8 * (k - 4) + z) * SW + jj] = cur[o];
            }
        }
        if (k <= 6) {
            for (int o = tid; o < 64; o += 128) {
                const int z = o >> 3, zz = o & 7;
                float s = 0.f;
                for (int j = 0; j < SD; j++) s += cur[z * SD + j] * (DTC * W2[j * HID + zz]);
                g_V[k * 64 + o] = s;
            }
        }
        __syncthreads();
    }

    for (int o = tid; o < 32 * 32; o += 128) {
        const int l = o >> 5, cidx = o & 31;
        const int m = cidx >> 3, zz = cidx & 7;
        const int i = l >> 3, z = l & 7;
        const int d = 3 + i - m;
        g_R[(size_t)(100 + l) * SW + 100 + cidx] = g_V[d * 64 + z * HID + zz];
    }
}

__device__ __forceinline__ float matvec100(const float4* at4s, const float4* v4, int i) {
    float acc = 0.f;
#pragma unroll
    for (int j4 = 0; j4 < 25; j4++) {
        float4 m = at4s[j4 * SD + i];
        float4 x = v4[j4];
        acc = fmaf(m.x, x.x, acc); acc = fmaf(m.y, x.y, acc);
        acc = fmaf(m.z, x.z, acc); acc = fmaf(m.w, x.w, acc);
    }
    return acc;
}

// ============================================================================
// 2) precomp: P_b and q0..q3 per 4-step block
// ============================================================================
__global__ void __launch_bounds__(128, 1) precomp_kernel(
    const float* __restrict__ w, const float* __restrict__ u,
    const float* __restrict__ Bw, const float* __restrict__ W1,
    const float* __restrict__ b1, const float* __restrict__ b2)
{
    __shared__ __align__(16) float4 at4s[SD * 25];
    __shared__ float W1sm[SD * HID];
    __shared__ __align__(16) float va[SD];
    __shared__ __align__(16) float vb[SD];

    const int tid = threadIdx.x;
    const float4* gAt4 = reinterpret_cast<const float4*>(g_At4);
    for (int o = tid; o < SD * 25; o += 128) at4s[o] = gAt4[o];
    for (int o = tid; o < SD * HID; o += 128) W1sm[o] = W1[o];

    float bwx = 0.f, bwy = 0.f, db2 = 0.f;
    if (tid < SD) { bwx = Bw[tid * 2]; bwy = Bw[tid * 2 + 1]; db2 = DTC * b2[tid]; }
    float b1z = 0.f;
    if (tid >= 104 && tid < 112) b1z = b1[tid - 104];
    __syncthreads();

    const float4* va4 = reinterpret_cast<const float4*>(va);
    const float4* vb4 = reinterpret_cast<const float4*>(vb);

    for (int gi = 0; gi < GQ; gi++) {
        const int b = blockIdx.x * GQ + gi;
        const size_t k = 4 * (size_t)b;

#define INW(t)  ((size_t)(((t) <= TT ? (t) : TT) - 1))
        if (tid < SD)
            va[tid] = bwx * w[INW(k + 1) * 2] + bwy * w[INW(k + 1) * 2 + 1]
                    + u[INW(k + 1) * SD + tid] + db2;
        __syncthreads();
        if (tid < SD)
            vb[tid] = matvec100(at4s, va4, tid)
                    + bwx * w[INW(k + 2) * 2] + bwy * w[INW(k + 2) * 2 + 1]
                    + u[INW(k + 2) * SD + tid] + db2;
        __syncthreads();
        if (tid < SD)
            va[tid] = matvec100(at4s, vb4, tid)
                    + bwx * w[INW(k + 3) * 2] + bwy * w[INW(k + 3) * 2 + 1]
                    + u[INW(k + 3) * SD + tid] + db2;
        __syncthreads();
        if (tid < SD)
            vb[tid] = matvec100(at4s, va4, tid)
                    + bwx * w[INW(k + 4) * 2] + bwy * w[INW(k + 4) * 2 + 1]
                    + u[INW(k + 4) * SD + tid] + db2;
        __syncthreads();
        if (tid < SD) {
            g_P4[(size_t)b * SD + tid] = vb[tid];
            va[tid] = matvec100(at4s, vb4, tid)
                    + bwx * w[INW(k + 5) * 2] + bwy * w[INW(k + 5) * 2 + 1]
                    + u[INW(k + 5) * SD + tid] + db2;
        } else if (tid >= 104 && tid < 112) {
            const int z = tid - 104;
            float s = b1z;
#pragma unroll 4
            for (int j = 0; j < SD; j++) s += W1sm[z * SD + j] * vb[j];
            g_Qq[(size_t)b * 32 + z] = s;
        }
        __syncthreads();
        if (tid < SD)
            vb[tid] = matvec100(at4s, va4, tid)
                    + bwx * w[INW(k + 6) * 2] + bwy * w[INW(k + 6) * 2 + 1]
                    + u[INW(k + 6) * SD + tid] + db2;
        else if (tid >= 104 && tid < 112) {
            const int z = tid - 104;
            float s = b1z;
#pragma unroll 4
            for (int j = 0; j < SD; j++) s += W1sm[z * SD + j] * va[j];
            g_Qq[(size_t)b * 32 + 8 + z] = s;
        }
        __syncthreads();
        if (tid < SD)
            va[tid] = matvec100(at4s, vb4, tid)
                    + bwx * w[INW(k + 7) * 2] + bwy * w[INW(k + 7) * 2 + 1]
                    + u[INW(k + 7) * SD + tid] + db2;
        else if (tid >= 104 && tid < 112) {
            const int z = tid - 104;
            float s = b1z;
#pragma unroll 4
            for (int j = 0; j < SD; j++) s += W1sm[z * SD + j] * vb[j];
            g_Qq[(size_t)b * 32 + 16 + z] = s;
        }
        __syncthreads();
        if (tid >= 104 && tid < 112) {
            const int z = tid - 104;
            float s = b1z;
#pragma unroll 4
            for (int j = 0; j < SD; j++) s += W1sm[z * SD + j] * va[j];
            g_Qq[(size_t)b * 32 + 24 + z] = s;
        }
        __syncthreads();
#undef INW
    }
}

// ============================================================================
// 3) serial: 16384 four-step phases, 192 threads.
//    Producer/consumer named barriers WITH credit back-edges (one-ahead max):
//      bar2 (160): chain ARRIVE (h ready)      ; g+w4 SYNC.   [seeded by chain]
//      bar5 (160): g+w4 ARRIVE (credit, after bar2 sync) ; chain SYNC. [no seed]
//      bar3 (160): full sync g+w4+w5 after c stores.
//      bar4 (64):  w5 ARRIVE (sPart ready)     ; chain SYNC.  [seeded by w5]
//      bar6 (64):  chain ARRIVE (credit, after bar4 sync) ; w5 SYNC.  [no seed]
// ============================================================================
__global__ void __launch_bounds__(192, 1) serial_kernel(const float* __restrict__ c0)
{
    __shared__ __align__(16) float sbuf[2][136];
    __shared__ float sPart[2][32];

    const int tid = threadIdx.x;
    const int wid = tid >> 5;
    const int l   = tid & 31;
    const bool isG     = (wid < 3);
    const bool isChain = (wid == 3);
    const bool isW4    = (wid == 4);
    const bool isP5    = (wid == 5);
    const int grp = l >> 3;
    const int seg = l & 7;

    // init S_0 = [c0 | h1 | h2 | h3 | h4]
    if (tid < SD)       sbuf[0][tid] = c0[tid];
    else if (tid < SW)  sbuf[0][tid] = g_h[(size_t)(1 + ((tid - 100) >> 3)) * HID + ((tid - 100) & 7)];
    else if (tid < 136) sbuf[0][tid] = 0.f;
    if (tid < 136) sbuf[1][tid] = 0.f;
    if (tid < 32) { sPart[0][tid] = 0.f; sPart[1][tid] = 0.f; }

    // weight overlay (union keeps register budget as R10)
    unsigned long long rva[66];
#pragma unroll
    for (int q = 0; q < 66; q++) rva[q] = 0ull;
    float cp0[8], cp1[8], cp2[8];
#pragma unroll
    for (int j = 0; j < 8; j++) { cp0[j] = 0.f; cp1[j] = 0.f; cp2[j] = 0.f; }

    if (isG) {
        const float* Rr = g_R + (size_t)tid * SW;
#pragma unroll
        for (int q = 0; q < 66; q++) rva[q] = pack2(Rr[2 * q], Rr[2 * q + 1]);
    } else if (isChain) {
        const float* Rr = g_R + (size_t)(100 + l) * SW;
#pragma unroll
        for (int q = 0; q < 16; q++) rva[q] = pack2(Rr[100 + 2 * q], Rr[100 + 2 * q + 1]);
        const int ii = l >> 3, z = l & 7;
#pragma unroll
        for (int j = 0; j < 8; j++) {
            cp0[j] = (ii > 0) ? g_V[(ii - 1) * 64 + z * HID + j] : 0.f;
            cp1[j] = (ii > 1) ? g_V[(ii - 2) * 64 + z * HID + j] : 0.f;
            cp2[j] = (ii > 2) ? g_V[(ii - 3) * 64 + z * HID + j] : 0.f;
        }
    } else if (isP5) {
        const float* Rr = g_R + (size_t)(100 + l) * SW;
#pragma unroll
        for (int q = 0; q < 50; q++) rva[q] = pack2(Rr[2 * q], Rr[2 * q + 1]);
    } else if (isW4) {
        const float* Rr = g_R + (size_t)(96 + grp) * SW;
#pragma unroll
        for (int k = 0; k < 9; k++) {
            const int idx = seg + 8 * k;
            if (idx < 66) rva[k] = pack2(Rr[2 * idx], Rr[2 * idx + 1]);
        }
    }

    // prefetch (depth 2)
    const float* pPtr = 0;
    float pc = 0.f, pn = 0.f;
    if (isG) {
        pc = g_P4[tid]; pn = g_P4[SD + tid];
        pPtr = g_P4 + 2 * SD + tid;
    } else if (isChain) {
        pc = g_Qq[l]; pn = g_Qq[32 + l];
        pPtr = g_Qq + 2 * 32 + l;
    } else if (isW4 && seg == 0) {
        pc = g_P4[96 + grp]; pn = g_P4[SD + 96 + grp];
        pPtr = g_P4 + 2 * SD + 96 + grp;
    }
    float* gPtr = g_G + SD + (isG ? tid : (96 + grp));
    float* hPtr = g_h + (size_t)(5 + grp) * HID + seg;

    __syncthreads();   // sbuf[0] visible

    // pre-loop shadows: g/w4 c-part accumulators vs sbuf[0]; w5 -> sPart[0]
    unsigned long long a0 = 0ull, a1 = 0ull, a2 = 0ull, a3 = 0ull;
    {
        const ulonglong2* sq = reinterpret_cast<const ulonglong2*>(sbuf[0]);
        if (isG) {
#pragma unroll
            for (int q = 0; q < 25; q++) {
                ulonglong2 gg = sq[q];
                if (q & 1) { fma2(a2, rva[2 * q], gg.x); fma2(a3, rva[2 * q + 1], gg.y); }
                else       { fma2(a0, rva[2 * q], gg.x); fma2(a1, rva[2 * q + 1], gg.y); }
            }
        } else if (isP5) {
            unsigned long long b0 = 0ull, b1 = 0ull, b2 = 0ull, b3 = 0ull;
#pragma unroll
            for (int q = 0; q < 25; q++) {
                ulonglong2 gg = sq[q];
                if (q & 1) { fma2(b2, rva[2 * q], gg.x); fma2(b3, rva[2 * q + 1], gg.y); }
                else       { fma2(b0, rva[2 * q], gg.x); fma2(b1, rva[2 * q + 1], gg.y); }
            }
            add2(b0, b1); add2(b2, b3); add2(b0, b2);
            float lo, hi; unpack2(b0, lo, hi);
            sPart[0][l] = lo + hi;
        } else if (isW4) {
            const unsigned long long* s1 = reinterpret_cast<const unsigned long long*>(sbuf[0]);
#pragma unroll
            for (int k = 0; k < 9; k++) {
                const int idx = seg + 8 * k;
                if (idx < 50) fma2(a0, rva[k], s1[idx]);
            }
        }
    }
    __syncthreads();   // sPart[0] + shadows visible

    // seed ONLY the data barriers (bar2 by chain, bar4 by w5); credits unseeded.
    if (isChain) asm volatile("bar.arrive 2, 160;" ::: "memory");  // h(S_0) in sbuf[0]
    if (isP5)    asm volatile("bar.arrive 4, 64;"  ::: "memory");  // sPart[0] ready

    if (isChain) {
        int p = 0;
        for (int b = 0; b < NB4; b++) {
            asm volatile("bar.sync 4, 64;" ::: "memory");     // sPart[p] ready
            asm volatile("bar.arrive 6, 64;" ::: "memory");   // credit to w5
            float pn2 = __ldcg(pPtr);
            const int np = p ^ 1;
            const float part = sPart[p][l];
            unsigned long long b0 = 0ull, b1 = 0ull;
            const ulonglong2* sp = reinterpret_cast<const ulonglong2*>(sbuf[p]);
#pragma unroll
            for (int m = 0; m < 8; m++) {
                ulonglong2 gg = sp[25 + m];
                fma2(b0, rva[2 * m], gg.x); fma2(b1, rva[2 * m + 1], gg.y);
            }
            add2(b0, b1);
            float lo, hi; unpack2(b0, lo, hi);
            float acc = part + lo + hi + pc;
            const float val0 = tanh_hw(acc);
            {
                float t0 = cp0[0] * __shfl_sync(0xffffffffu, val0, 0);
                float t1 = cp0[1] * __shfl_sync(0xffffffffu, val0, 1);
                float t2 = cp0[2] * __shfl_sync(0xffffffffu, val0, 2);
                float t3 = cp0[3] * __shfl_sync(0xffffffffu, val0, 3);
                float t4 = cp0[4] * __shfl_sync(0xffffffffu, val0, 4);
                float t5 = cp0[5] * __shfl_sync(0xffffffffu, val0, 5);
                float t6 = cp0[6] * __shfl_sync(0xffffffffu, val0, 6);
                float t7 = cp0[7] * __shfl_sync(0xffffffffu, val0, 7);
                acc += ((t0 + t1) + (t2 + t3)) + ((t4 + t5) + (t6 + t7));
            }
            const float val1 = tanh_hw(acc);
            {
                float t0 = cp1[0] * __shfl_sync(0xffffffffu, val1, 8);
                float t1 = cp1[1] * __shfl_sync(0xffffffffu, val1, 9);
                float t2 = cp1[2] * __shfl_sync(0xffffffffu, val1, 10);
                float t3 = cp1[3] * __shfl_sync(0xffffffffu, val1, 11);
                float t4 = cp1[4] * __shfl_sync(0xffffffffu, val1, 12);
                float t5 = cp1[5] * __shfl_sync(0xffffffffu, val1, 13);
                float t6 = cp1[6] * __shfl_sync(0xffffffffu, val1, 14);
                float t7 = cp1[7] * __shfl_sync(0xffffffffu, val1, 15);
                acc += ((t0 + t1) + (t2 + t3)) + ((t4 + t5) + (t6 + t7));
            }
            const float val2 = tanh_hw(acc);
            {
                float t0 = cp2[0] * __shfl_sync(0xffffffffu, val2, 16);
                float t1 = cp2[1] * __shfl_sync(0xffffffffu, val2, 17);
                float t2 = cp2[2] * __shfl_sync(0xffffffffu, val2, 18);
                float t3 = cp2[3] * __shfl_sync(0xffffffffu, val2, 19);
                float t4 = cp2[4] * __shfl_sync(0xffffffffu, val2, 20);
                float t5 = cp2[5] * __shfl_sync(0xffffffffu, val2, 21);
                float t6 = cp2[6] * __shfl_sync(0xffffffffu, val2, 22);
                float t7 = cp2[7] * __shfl_sync(0xffffffffu, val2, 23);
                acc += ((t0 + t1) + (t2 + t3)) + ((t4 + t5) + (t6 + t7));
            }
            const float val3 = tanh_hw(acc);
            const float hv = (l < 8) ? val0 : (l < 16) ? val1 : (l < 24) ? val2 : val3;
            sbuf[np][100 + l] = hv;
            *hPtr = hv; hPtr += 32;
            asm volatile("bar.sync 5, 160;" ::: "memory");    // credit from g+w4 (round b)
            asm volatile("bar.arrive 2, 160;" ::: "memory");  // publish h(S_{b+1})
            pc = pn; pn = pn2;
            if (b < NB4 - 3) pPtr += 32;
            p = np;
        }
    } else if (isG) {
        int p = 0;
        for (int b = 0; b < NB4; b++) {
            asm volatile("bar.sync 2, 160;" ::: "memory");    // h(S_b) ready
            asm volatile("bar.arrive 5, 160;" ::: "memory");  // credit to chain
            float pn2 = __ldcg(pPtr);
            const int np = p ^ 1;
            const ulonglong2* sp = reinterpret_cast<const ulonglong2*>(sbuf[p]);
#pragma unroll
            for (int q = 25; q < 33; q++) {
                ulonglong2 gg = sp[q];
                if (q & 1) { fma2(a2, rva[2 * q], gg.x); fma2(a3, rva[2 * q + 1], gg.y); }
                else       { fma2(a0, rva[2 * q], gg.x); fma2(a1, rva[2 * q + 1], gg.y); }
            }
            add2(a0, a1); add2(a2, a3); add2(a0, a2);
            float lo, hi; unpack2(a0, lo, hi);
            const float gn = lo + hi + pc;
            sbuf[np][tid] = gn;
            *gPtr = gn; gPtr += SD;
            asm volatile("bar.sync 3, 160;" ::: "memory");    // all c(S_{b+1}) stored
            a0 = 0ull; a1 = 0ull; a2 = 0ull; a3 = 0ull;
            const ulonglong2* sq = reinterpret_cast<const ulonglong2*>(sbuf[np]);
#pragma unroll
            for (int q = 0; q < 25; q++) {
                ulonglong2 gg = sq[q];
                if (q & 1) { fma2(a2, rva[2 * q], gg.x); fma2(a3, rva[2 * q + 1], gg.y); }
                else       { fma2(a0, rva[2 * q], gg.x); fma2(a1, rva[2 * q + 1], gg.y); }
            }
            pc = pn; pn = pn2;
            if (b < NB4 - 3) pPtr += SD;
            p = np;
        }
    } else if (isW4) {
        int p = 0;
        for (int b = 0; b < NB4; b++) {
            asm volatile("bar.sync 2, 160;" ::: "memory");
            asm volatile("bar.arrive 5, 160;" ::: "memory");  // credit to chain
            float pn2 = 0.f;
            if (pPtr) pn2 = __ldcg(pPtr);
            const int np = p ^ 1;
            const unsigned long long* s1 = reinterpret_cast<const unsigned long long*>(sbuf[p]);
#pragma unroll
            for (int k = 0; k < 9; k++) {
                const int idx = seg + 8 * k;
                if (idx >= 50 && idx < 66) fma2(a0, rva[k], s1[idx]);
            }
            float lo, hi; unpack2(a0, lo, hi);
            float v = lo + hi;
            v += __shfl_xor_sync(0xffffffffu, v, 1);
            v += __shfl_xor_sync(0xffffffffu, v, 2);
            v += __shfl_xor_sync(0xffffffffu, v, 4);
            if (seg == 0) {
                const float gn = v + pc;
                sbuf[np][96 + grp] = gn;
                *gPtr = gn;
            }
            gPtr += SD;
            asm volatile("bar.sync 3, 160;" ::: "memory");
            a0 = 0ull;
            const unsigned long long* s2 = reinterpret_cast<const unsigned long long*>(sbuf[np]);
#pragma unroll
            for (int k = 0; k < 9; k++) {
                const int idx = seg + 8 * k;
                if (idx < 50) fma2(a0, rva[k], s2[idx]);
            }
            pc = pn; pn = pn2;
            if (pPtr && b < NB4 - 3) pPtr += SD;
            p = np;
        }
    } else { // isP5
        int p = 0;
        for (int b = 0; b < NB4; b++) {
            asm volatile("bar.sync 3, 160;" ::: "memory");    // c(S_{b+1}) ready
            const int np = p ^ 1;
            unsigned long long b0 = 0ull, b1 = 0ull, b2 = 0ull, b3 = 0ull;
            const ulonglong2* sq = reinterpret_cast<const ulonglong2*>(sbuf[np]);
#pragma unroll
            for (int q = 0; q < 25; q++) {
                ulonglong2 gg = sq[q];
                if (q & 1) { fma2(b2, rva[2 * q], gg.x); fma2(b3, rva[2 * q + 1], gg.y); }
                else       { fma2(b0, rva[2 * q], gg.x); fma2(b1, rva[2 * q + 1], gg.y); }
            }
            add2(b0, b1); add2(b2, b3); add2(b0, b2);
            float lo, hi; unpack2(b0, lo, hi);
            sPart[np][l] = lo + hi;
            asm volatile("bar.sync 6, 64;" ::: "memory");     // credit from chain
            asm volatile("bar.arrive 4, 64;" ::: "memory");   // sPart(S_{b+1}) ready
            p = np;
        }
    }
}

// ============================================================================
// 4) post: reconstruct c_{4m+1..3} from anchors + h; anchor m+1 row; y.
// ============================================================================
__global__ void __launch_bounds__(128, 1) post_kernel(
    const float* __restrict__ w, const float* __restrict__ u,
    const float* __restrict__ Bw, const float* __restrict__ W2,
    const float* __restrict__ b2, const int* __restrict__ obs,
    float* __restrict__ outc, float* __restrict__ outy)
{
    __shared__ __align__(16) float4 at4s[SD * 25];
    __shared__ __align__(16) float va[SD];
    __shared__ float hh[32];
    __shared__ int obsS[NOBS];

    const int tid = threadIdx.x;
    const float4* gAt4 = reinterpret_cast<const float4*>(g_At4);
    for (int o = tid; o < SD * 25; o += 128) at4s[o] = gAt4[o];
    if (tid < NOBS) obsS[tid] = obs[tid];

    float bwx = 0.f, bwy = 0.f, db2 = 0.f, w2r[HID];
#pragma unroll
    for (int z = 0; z < HID; z++) w2r[z] = 0.f;
    if (tid < SD) {
        bwx = Bw[tid * 2]; bwy = Bw[tid * 2 + 1]; db2 = DTC * b2[tid];
#pragma unroll
        for (int z = 0; z < HID; z++) w2r[z] = DTC * W2[tid * HID + z];
    }
    __syncthreads();

    const float4* va4 = reinterpret_cast<const float4*>(va);

    for (int gi = 0; gi < GQ; gi++) {
        const int m = blockIdx.x * GQ + gi;
        const int t0 = 4 * m;

        if (tid < 32) hh[tid] = g_h[(size_t)(t0 + 1 + (tid >> 3)) * HID + (tid & 7)];
        if (tid < SD) va[tid] = g_G[(size_t)m * SD + tid];
        __syncthreads();
#pragma unroll
        for (int s = 1; s <= 3; s++) {
            const int t = t0 + s;
            float cv = 0.f;
            if (tid < SD) {
                cv = matvec100(at4s, va4, tid)
                   + bwx * w[2 * (t - 1)] + bwy * w[2 * (t - 1) + 1]
                   + u[(size_t)(t - 1) * SD + tid] + db2;
#pragma unroll
                for (int z = 0; z < HID; z++) cv += w2r[z] * hh[8 * (s - 1) + z];
            }
            __syncthreads();
            if (tid < SD) {
                va[tid] = cv;
                outc[(size_t)(t - 1) * SD + tid] = cv;
            }
            __syncthreads();
            if (tid < NOBS) outy[(size_t)(t - 1) * NOBS + tid] = va[obsS[tid]];
        }
        __syncthreads();
        if (tid < SD) {
            float cv = g_G[(size_t)(m + 1) * SD + tid];
            va[tid] = cv;
            outc[(size_t)(t0 + 3) * SD + tid] = cv;
        }
        __syncthreads();
        if (tid < NOBS) outy[(size_t)(t0 + 3) * NOBS + tid] = va[obsS[tid]];
        __syncthreads();
    }
}

extern "C" void kernel_launch(void* const* d_in, const int* in_sizes, int n_in,
                              void* d_out, int out_size) {
    const float* c0  = (const float*)d_in[0];
    const float* w   = (const float*)d_in[1];
    const float* u   = (const float*)d_in[2];
    const float* A   = (const float*)d_in[3];
    const float* Bw  = (const float*)d_in[4];
    const float* W1  = (const float*)d_in[5];
    const float* b1  = (const float*)d_in[6];
    const float* W2  = (const float*)d_in[7];
    const float* b2  = (const float*)d_in[8];
    const int*   ob  = (const int*)d_in[9];

    float* outc = (float*)d_out;                      // (T, 100)
    float* outy = (float*)d_out + (size_t)TT * SD;    // (T, 12)

    setup1_kernel<<<1, 128>>>(A, Bw, W1, b1, W2, b2, c0, w, u);
    setup2_kernel<<<1, 128>>>(A, W1, W2);
    precomp_kernel<<<PRE_CTAS, 128>>>(w, u, Bw, W1, b1, b2);
    serial_kernel<<<1, 192>>>(c0);
    post_kernel<<<POST_CTAS, 128>>>(w, u, Bw, W2, b2, ob, outc, outy);
}

// round 14
// speedup vs baseline: 1.1549x; 1.0156x over previous
#include <cuda_runtime.h>

#define TT    65536
#define NB4   16384          /* 4*NB4 = 65536 serial 4-step blocks */
#define SD    100
#define HID   8
#define NOBS  12
#define DTC   0.01f
#define SW    132            /* state width */
#define GQ    8
#define PRE_CTAS  (NB4 / GQ) /* 2048, exact */
#define POST_CTAS (NB4 / GQ) /* 2048, exact */

__device__ __forceinline__ unsigned long long pack2(float lo, float hi) {
    unsigned long long r;
    asm("mov.b64 %0, {%1, %2};" : "=l"(r) : "f"(lo), "f"(hi));
    return r;
}
__device__ __forceinline__ void unpack2(unsigned long long v, float& lo, float& hi) {
    asm("mov.b64 {%0, %1}, %2;" : "=f"(lo), "=f"(hi) : "l"(v));
}
__device__ __forceinline__ void fma2(unsigned long long& acc, unsigned long long a, unsigned long long b) {
    asm("fma.rn.f32x2 %0, %1, %2, %0;" : "+l"(acc) : "l"(a), "l"(b));
}
__device__ __forceinline__ void add2(unsigned long long& acc, unsigned long long b) {
    asm("add.rn.f32x2 %0, %0, %1;" : "+l"(acc) : "l"(b));
}
__device__ __forceinline__ float tanh_hw(float x) {
    float r;
    asm("tanh.approx.f32 %0, %1;" : "=f"(r) : "f"(x));
    return r;
}

// ------------------------- device scratch -------------------------
__device__ float g_R[132 * SW];          // rows 0-99: c-rows; 100-131: chain rows
__device__ float g_Rp[32 * SW];          // R' = Rc(32x100) @ M(100x132)
__device__ float g_sPart0[32];           // Rc @ c0
__device__ float g_At4[SD * SD];         // A in float4-interleaved matvec layout
__device__ float g_U1[SD * HID];         // dt A W2
__device__ float g_U2[SD * HID];         // dt A^2 W2
__device__ float g_V[7 * 64];            // V_j = dt W1 A^j W2, j=0..6
__device__ float g_P4[(size_t)NB4 * SD];
__device__ float g_Qq[(size_t)NB4 * 32]; // q0|q1|q2|q3 per block
__device__ float g_Qf[(size_t)NB4 * 32]; // qFold_b = q_b + Rc @ P_{b-1}
__device__ float g_G[(size_t)(NB4 + 1) * SD];   // anchors c_{4b} (row 0 = c0)
__device__ float g_h[(size_t)(TT + 9) * HID];   // h_t rows

// ============================================================================
// 1a) setup1 (1 CTA): c-rows [A^4 | dtA^3W2 | dtA^2W2 | dtAW2 | dtW2],
//     At4 layout, initial rollout h1..h4, anchor row 0.
// ============================================================================
__global__ void __launch_bounds__(128, 1) setup1_kernel(
    const float* __restrict__ A,  const float* __restrict__ Bw,
    const float* __restrict__ W1, const float* __restrict__ b1,
    const float* __restrict__ W2, const float* __restrict__ b2,
    const float* __restrict__ c0, const float* __restrict__ w,
    const float* __restrict__ u)
{
    __shared__ float As[SD * SD];
    __shared__ float W2d[SD * HID];
    __shared__ float W1s[SD * HID];
    __shared__ float cva[SD];
    __shared__ float cvb[SD];
    __shared__ float hh[HID];

    const int tid = threadIdx.x;

    for (int i = tid; i < SD * SD; i += 128) As[i] = A[i];
    for (int i = tid; i < SD * HID; i += 128) W2d[i] = DTC * W2[i];
    for (int i = tid; i < SD * HID; i += 128) W1s[i] = W1[i];
    if (tid < SD) { cva[tid] = c0[tid]; g_G[tid] = c0[tid]; }
    __syncthreads();
    for (int o = tid; o < SD * SD; o += 128) {
        int j4 = o / 400, rem = o % 400, i = rem / 4, r = rem % 4;
        g_At4[o] = As[i * SD + 4 * j4 + r];
    }

    // initial rollout
    float* cc = cva; float* cn = cvb;
    for (int t = 1; t <= 4; t++) {
        if (tid >= 104 && tid < 112) {
            const int z = tid - 104;
            float s = b1[z];
            for (int k = 0; k < SD; k++) s += W1s[z * SD + k] * cc[k];
            float ht = tanh_hw(s);
            hh[z] = ht;
            g_h[(size_t)t * HID + z] = ht;
        }
        __syncthreads();
        if (t < 4 && tid < SD) {
            const int i = tid;
            float s = Bw[i * 2] * w[(t - 1) * 2] + Bw[i * 2 + 1] * w[(t - 1) * 2 + 1]
                    + u[(size_t)(t - 1) * SD + i] + DTC * b2[i];
            for (int j = 0; j < SD; j++) s += As[i * SD + j] * cc[j];
#pragma unroll
            for (int z = 0; z < HID; z++) s += W2d[i * HID + z] * hh[z];
            cn[i] = s;
        }
        __syncthreads();
        float* t2 = cc; cc = cn; cn = t2;
    }

    float ra[SD], rb[SD];
    float u1r[HID], u2r[HID];
    if (tid < SD) {
        const int i = tid;
#pragma unroll
        for (int jj = 0; jj < SD; jj++) ra[jj] = 0.f;
#pragma unroll
        for (int z = 0; z < HID; z++) u1r[z] = 0.f;
        for (int j = 0; j < SD; j++) {
            const float a = As[i * SD + j];
#pragma unroll
            for (int jj = 0; jj < SD; jj++) ra[jj] += a * As[j * SD + jj];
#pragma unroll
            for (int z = 0; z < HID; z++) u1r[z] += a * W2d[j * HID + z];
        }
#pragma unroll
        for (int z = 0; z < HID; z++) g_U1[i * HID + z] = u1r[z];
#pragma unroll
        for (int jj = 0; jj < SD; jj++) rb[jj] = 0.f;
        for (int j = 0; j < SD; j++) {
            const float a = ra[j];
#pragma unroll
            for (int jj = 0; jj < SD; jj++) rb[jj] += a * As[j * SD + jj];
        }
#pragma unroll
        for (int jj = 0; jj < SD; jj++) ra[jj] = 0.f;
        for (int j = 0; j < SD; j++) {
            const float a = rb[j];
#pragma unroll
            for (int jj = 0; jj < SD; jj++) ra[jj] += a * As[j * SD + jj];
        }
        for (int jj = 0; jj < SD; jj++) g_R[i * SW + jj] = ra[jj];
    }
    __syncthreads();
    for (int o = tid; o < SD * HID; o += 128) W1s[o] = g_U1[o];
    __syncthreads();
    if (tid < SD) {
        const int i = tid;
#pragma unroll
        for (int z = 0; z < HID; z++) u2r[z] = 0.f;
        for (int j = 0; j < SD; j++) {
            const float a = As[i * SD + j];
#pragma unroll
            for (int z = 0; z < HID; z++) u2r[z] += a * W1s[j * HID + z];
        }
#pragma unroll
        for (int z = 0; z < HID; z++) g_U2[i * HID + z] = u2r[z];
    }
    __syncthreads();
    for (int o = tid; o < SD * HID; o += 128) W1s[o] = g_U2[o];
    __syncthreads();
    if (tid < SD) {
        const int i = tid;
        float u3r[HID];
#pragma unroll
        for (int z = 0; z < HID; z++) u3r[z] = 0.f;
        for (int j = 0; j < SD; j++) {
            const float a = As[i * SD + j];
#pragma unroll
            for (int z = 0; z < HID; z++) u3r[z] += a * W1s[j * HID + z];
        }
#pragma unroll
        for (int z = 0; z < HID; z++) {
            g_R[i * SW + 100 + z] = u3r[z];
            g_R[i * SW + 108 + z] = u2r[z];
            g_R[i * SW + 116 + z] = u1r[z];
            g_R[i * SW + 124 + z] = W2d[i * HID + z];
        }
    }
}

// ============================================================================
// 1b) setup2 (1 CTA): chain rows (W1A^{4+i} heads, V tails) + V tables.
// ============================================================================
__global__ void __launch_bounds__(128, 1) setup2_kernel(
    const float* __restrict__ A, const float* __restrict__ W1,
    const float* __restrict__ W2)
{
    __shared__ float As[SD * SD];
    __shared__ float bufA[SD * HID];
    __shared__ float bufB[SD * HID];

    const int tid = threadIdx.x;
    for (int i = tid; i < SD * SD; i += 128) As[i] = A[i];
    for (int i = tid; i < SD * HID; i += 128) bufA[i] = W1[i];
    __syncthreads();

    float* cur = bufA;
    float* nxt = bufB;

    for (int o = tid; o < 64; o += 128) {
        const int z = o >> 3, zz = o & 7;
        float s = 0.f;
        for (int j = 0; j < SD; j++) s += cur[z * SD + j] * (DTC * W2[j * HID + zz]);
        g_V[o] = s;
    }
    __syncthreads();

    for (int k = 1; k <= 7; k++) {
        for (int o = tid; o < SD * HID; o += 128) {
            const int z = o / SD, jj = o % SD;
            float s = 0.f;
            for (int j = 0; j < SD; j++) s += cur[z * SD + j] * As[j * SD + jj];
            nxt[o] = s;
        }
        __syncthreads();
        float* t = cur; cur = nxt; nxt = t;
        if (k >= 4) {
            for (int o = tid; o < SD * HID; o += 128) {
                const int z = o / SD, jj = o % SD;
                g_R[(size_t)(100 + 8 * (k - 4) + z) * SW + jj] = cur[o];
            }
        }
        if (k <= 6) {
            for (int o = tid; o < 64; o += 128) {
                const int z = o >> 3, zz = o & 7;
                float s = 0.f;
                for (int j = 0; j < SD; j++) s += cur[z * SD + j] * (DTC * W2[j * HID + zz]);
                g_V[k * 64 + o] = s;
            }
        }
        __syncthreads();
    }

    for (int o = tid; o < 32 * 32; o += 128) {
        const int l = o >> 5, cidx = o & 31;
        const int m = cidx >> 3, zz = cidx & 7;
        const int i = l >> 3, z = l & 7;
        const int d = 3 + i - m;
        g_R[(size_t)(100 + l) * SW + 100 + cidx] = g_V[d * 64 + z * HID + zz];
    }
}

// ============================================================================
// 1c) setup3 (1 CTA): R' = Rc @ M (32x132) and sPart0 = Rc @ c0.
//     Runs after setup1+setup2 (needs full g_R).
// ============================================================================
__global__ void __launch_bounds__(128, 1) setup3_kernel(const float* __restrict__ c0)
{
    __shared__ float RcS[32 * 100];
    __shared__ float MgS[25 * 132];
    const int tid = threadIdx.x;
    for (int i = tid; i < 3200; i += 128)
        RcS[i] = g_R[(size_t)(100 + i / 100) * SW + (i % 100)];

    const int r = tid >> 2, s = tid & 3;
    float acc[33];
#pragma unroll
    for (int k = 0; k < 33; k++) acc[k] = 0.f;

    for (int q0 = 0; q0 < 100; q0 += 25) {
        __syncthreads();
        for (int e = tid; e < 25 * 132; e += 128)
            MgS[e] = g_R[(size_t)(q0 + e / 132) * SW + (e % 132)];
        __syncthreads();
        for (int j = 0; j < 25; j++) {
            const float rc = RcS[r * 100 + q0 + j];
#pragma unroll
            for (int k = 0; k < 33; k++)
                acc[k] += rc * MgS[j * 132 + s + 4 * k];
        }
    }
    for (int k = 0; k < 33; k++)
        g_Rp[(size_t)r * SW + s + 4 * k] = acc[k];

    float sum = 0.f;
    for (int j = s * 25; j < s * 25 + 25; j++) sum += RcS[r * 100 + j] * c0[j];
    sum += __shfl_xor_sync(0xffffffffu, sum, 1);
    sum += __shfl_xor_sync(0xffffffffu, sum, 2);
    if (s == 0) g_sPart0[r] = sum;
}

__device__ __forceinline__ float matvec100(const float4* at4s, const float4* v4, int i) {
    float acc = 0.f;
#pragma unroll
    for (int j4 = 0; j4 < 25; j4++) {
        float4 m = at4s[j4 * SD + i];
        float4 x = v4[j4];
        acc = fmaf(m.x, x.x, acc); acc = fmaf(m.y, x.y, acc);
        acc = fmaf(m.z, x.z, acc); acc = fmaf(m.w, x.w, acc);
    }
    return acc;
}

// ============================================================================
// 2) precomp: P_b and q0..q3 per 4-step block
// ============================================================================
__global__ void __launch_bounds__(128, 1) precomp_kernel(
    const float* __restrict__ w, const float* __restrict__ u,
    const float* __restrict__ Bw, const float* __restrict__ W1,
    const float* __restrict__ b1, const float* __restrict__ b2)
{
    __shared__ __align__(16) float4 at4s[SD * 25];
    __shared__ float W1sm[SD * HID];
    __shared__ __align__(16) float va[SD];
    __shared__ __align__(16) float vb[SD];

    const int tid = threadIdx.x;
    const float4* gAt4 = reinterpret_cast<const float4*>(g_At4);
    for (int o = tid; o < SD * 25; o += 128) at4s[o] = gAt4[o];
    for (int o = tid; o < SD * HID; o += 128) W1sm[o] = W1[o];

    float bwx = 0.f, bwy = 0.f, db2 = 0.f;
    if (tid < SD) { bwx = Bw[tid * 2]; bwy = Bw[tid * 2 + 1]; db2 = DTC * b2[tid]; }
    float b1z = 0.f;
    if (tid >= 104 && tid < 112) b1z = b1[tid - 104];
    __syncthreads();

    const float4* va4 = reinterpret_cast<const float4*>(va);
    const float4* vb4 = reinterpret_cast<const float4*>(vb);

    for (int gi = 0; gi < GQ; gi++) {
        const int b = blockIdx.x * GQ + gi;
        const size_t k = 4 * (size_t)b;

#define INW(t)  ((size_t)(((t) <= TT ? (t) : TT) - 1))
        if (tid < SD)
            va[tid] = bwx * w[INW(k + 1) * 2] + bwy * w[INW(k + 1) * 2 + 1]
                    + u[INW(k + 1) * SD + tid] + db2;
        __syncthreads();
        if (tid < SD)
            vb[tid] = matvec100(at4s, va4, tid)
                    + bwx * w[INW(k + 2) * 2] + bwy * w[INW(k + 2) * 2 + 1]
                    + u[INW(k + 2) * SD + tid] + db2;
        __syncthreads();
        if (tid < SD)
            va[tid] = matvec100(at4s, vb4, tid)
                    + bwx * w[INW(k + 3) * 2] + bwy * w[INW(k + 3) * 2 + 1]
                    + u[INW(k + 3) * SD + tid] + db2;
        __syncthreads();
        if (tid < SD)
            vb[tid] = matvec100(at4s, va4, tid)
                    + bwx * w[INW(k + 4) * 2] + bwy * w[INW(k + 4) * 2 + 1]
                    + u[INW(k + 4) * SD + tid] + db2;
        __syncthreads();
        if (tid < SD) {
            g_P4[(size_t)b * SD + tid] = vb[tid];
            va[tid] = matvec100(at4s, vb4, tid)
                    + bwx * w[INW(k + 5) * 2] + bwy * w[INW(k + 5) * 2 + 1]
                    + u[INW(k + 5) * SD + tid] + db2;
        } else if (tid >= 104 && tid < 112) {
            const int z = tid - 104;
            float s = b1z;
#pragma unroll 4
            for (int j = 0; j < SD; j++) s += W1sm[z * SD + j] * vb[j];
            g_Qq[(size_t)b * 32 + z] = s;
        }
        __syncthreads();
        if (tid < SD)
            vb[tid] = matvec100(at4s, va4, tid)
                    + bwx * w[INW(k + 6) * 2] + bwy * w[INW(k + 6) * 2 + 1]
                    + u[INW(k + 6) * SD + tid] + db2;
        else if (tid >= 104 && tid < 112) {
            const int z = tid - 104;
            float s = b1z;
#pragma unroll 4
            for (int j = 0; j < SD; j++) s += W1sm[z * SD + j] * va[j];
            g_Qq[(size_t)b * 32 + 8 + z] = s;
        }
        __syncthreads();
        if (tid < SD)
            va[tid] = matvec100(at4s, vb4, tid)
                    + bwx * w[INW(k + 7) * 2] + bwy * w[INW(k + 7) * 2 + 1]
                    + u[INW(k + 7) * SD + tid] + db2;
        else if (tid >= 104 && tid < 112) {
            const int z = tid - 104;
            float s = b1z;
#pragma unroll 4
            for (int j = 0; j < SD; j++) s += W1sm[z * SD + j] * vb[j];
            g_Qq[(size_t)b * 32 + 16 + z] = s;
        }
        __syncthreads();
        if (tid >= 104 && tid < 112) {
            const int z = tid - 104;
            float s = b1z;
#pragma unroll 4
            for (int j = 0; j < SD; j++) s += W1sm[z * SD + j] * va[j];
            g_Qq[(size_t)b * 32 + 24 + z] = s;
        }
        __syncthreads();
#undef INW
    }
}

// ============================================================================
// 2b) fold: g_Qf[b] = g_Qq[b] + Rc @ P_{b-1}  (b=0: no fold)
// ============================================================================
__global__ void __launch_bounds__(128, 1) fold_kernel()
{
    __shared__ float RcS[32 * 100];
    __shared__ float Ps[SD];
    const int tid = threadIdx.x;
    for (int i = tid; i < 3200; i += 128)
        RcS[i] = g_R[(size_t)(100 + i / 100) * SW + (i % 100)];
    const int r = tid >> 2, s = tid & 3;

    for (int gi = 0; gi < GQ; gi++) {
        const int b = blockIdx.x * GQ + gi;
        __syncthreads();
        if (b > 0 && tid < SD) Ps[tid] = g_P4[(size_t)(b - 1) * SD + tid];
        __syncthreads();
        float add = 0.f;
        if (b > 0) {
            float sum = 0.f;
            for (int j = s * 25; j < s * 25 + 25; j++) sum += RcS[r * 100 + j] * Ps[j];
            sum += __shfl_xor_sync(0xffffffffu, sum, 1);
            sum += __shfl_xor_sync(0xffffffffu, sum, 2);
            add = sum;
        }
        if (s == 0) g_Qf[(size_t)b * 32 + r] = g_Qq[(size_t)b * 32 + r] + add;
        __syncthreads();
    }
}

// ============================================================================
// 3) serial: 16384 four-step phases, 192 threads.
//    w5 now computes sPart_{b+1} = R' @ S_b DIRECTLY from sbuf[p] — it is off
//    the chain's critical ring. Barriers (counts as R13, tokens audited):
//      bar2 (160): chain ARRIVE (h ready)            ; g+w4 SYNC. [seeded]
//      bar5 (160): g+w4 ARRIVE (credit after bar2)   ; chain SYNC (early).
//      bar3 (160): full sync g+w4+w5 (phase pacing).
//      bar4 (64):  w5 ARRIVE (sPart ready)           ; chain SYNC. [seeded]
//      bar6 (64):  chain ARRIVE (slot credit)        ; w5 SYNC before STS.
// ============================================================================
__global__ void __launch_bounds__(192, 1) serial_kernel(const float* __restrict__ c0)
{
    __shared__ __align__(16) float sbuf[2][136];
    __shared__ float sPart[2][32];

    const int tid = threadIdx.x;
    const int wid = tid >> 5;
    const int l   = tid & 31;
    const bool isG     = (wid < 3);
    const bool isChain = (wid == 3);
    const bool isW4    = (wid == 4);
    const bool isP5    = (wid == 5);
    const int grp = l >> 3;
    const int seg = l & 7;

    // init S_0 = [c0 | h1 | h2 | h3 | h4]
    if (tid < SD)       sbuf[0][tid] = c0[tid];
    else if (tid < SW)  sbuf[0][tid] = g_h[(size_t)(1 + ((tid - 100) >> 3)) * HID + ((tid - 100) & 7)];
    else if (tid < 136) sbuf[0][tid] = 0.f;
    if (tid < 136) sbuf[1][tid] = 0.f;
    if (isP5) { sPart[0][l] = g_sPart0[l]; sPart[1][l] = 0.f; }

    // weight overlay (union keeps register budget)
    unsigned long long rva[66];
#pragma unroll
    for (int q = 0; q < 66; q++) rva[q] = 0ull;
    float cp0[8], cp1[8], cp2[8];
#pragma unroll
    for (int j = 0; j < 8; j++) { cp0[j] = 0.f; cp1[j] = 0.f; cp2[j] = 0.f; }

    if (isG) {
        const float* Rr = g_R + (size_t)tid * SW;
#pragma unroll
        for (int q = 0; q < 66; q++) rva[q] = pack2(Rr[2 * q], Rr[2 * q + 1]);
    } else if (isChain) {
        const float* Rr = g_R + (size_t)(100 + l) * SW;
#pragma unroll
        for (int q = 0; q < 16; q++) rva[q] = pack2(Rr[100 + 2 * q], Rr[100 + 2 * q + 1]);
        const int ii = l >> 3, z = l & 7;
#pragma unroll
        for (int j = 0; j < 8; j++) {
            cp0[j] = (ii > 0) ? g_V[(ii - 1) * 64 + z * HID + j] : 0.f;
            cp1[j] = (ii > 1) ? g_V[(ii - 2) * 64 + z * HID + j] : 0.f;
            cp2[j] = (ii > 2) ? g_V[(ii - 3) * 64 + z * HID + j] : 0.f;
        }
    } else if (isP5) {
        const float* Rr = g_Rp + (size_t)l * SW;
#pragma unroll
        for (int q = 0; q < 66; q++) rva[q] = pack2(Rr[2 * q], Rr[2 * q + 1]);
    } else if (isW4) {
        const float* Rr = g_R + (size_t)(96 + grp) * SW;
#pragma unroll
        for (int k = 0; k < 9; k++) {
            const int idx = seg + 8 * k;
            if (idx < 66) rva[k] = pack2(Rr[2 * idx], Rr[2 * idx + 1]);
        }
    }

    // prefetch (depth 2)
    const float* pPtr = 0;
    float pc = 0.f, pn = 0.f;
    if (isG) {
        pc = g_P4[tid]; pn = g_P4[SD + tid];
        pPtr = g_P4 + 2 * SD + tid;
    } else if (isChain) {
        pc = g_Qf[l]; pn = g_Qf[32 + l];
        pPtr = g_Qf + 2 * 32 + l;
    } else if (isW4 && seg == 0) {
        pc = g_P4[96 + grp]; pn = g_P4[SD + 96 + grp];
        pPtr = g_P4 + 2 * SD + 96 + grp;
    }
    float* gPtr = g_G + SD + (isG ? tid : (96 + grp));
    float* hPtr = g_h + (size_t)(5 + grp) * HID + seg;

    __syncthreads();   // sbuf[0] + sPart[0] visible

    // pre-loop shadows: g/w4 c-part accumulators vs sbuf[0]
    unsigned long long a0 = 0ull, a1 = 0ull, a2 = 0ull, a3 = 0ull;
    {
        const ulonglong2* sq = reinterpret_cast<const ulonglong2*>(sbuf[0]);
        if (isG) {
#pragma unroll
            for (int q = 0; q < 25; q++) {
                ulonglong2 gg = sq[q];
                if (q & 1) { fma2(a2, rva[2 * q], gg.x); fma2(a3, rva[2 * q + 1], gg.y); }
                else       { fma2(a0, rva[2 * q], gg.x); fma2(a1, rva[2 * q + 1], gg.y); }
            }
        } else if (isW4) {
            const unsigned long long* s1 = reinterpret_cast<const unsigned long long*>(sbuf[0]);
#pragma unroll
            for (int k = 0; k < 9; k++) {
                const int idx = seg + 8 * k;
                if (idx < 50) fma2(a0, rva[k], s1[idx]);
            }
        }
    }
    __syncthreads();

    // seed ONLY the data barriers (bar2 by chain, bar4 by w5); credits unseeded.
    if (isChain) asm volatile("bar.arrive 2, 160;" ::: "memory");  // h(S_0) in sbuf[0]
    if (isP5)    asm volatile("bar.arrive 4, 64;"  ::: "memory");  // sPart[0] ready

    if (isChain) {
        int p = 0;
        for (int b = 0; b < NB4; b++) {
            asm volatile("bar.sync 4, 64;" ::: "memory");     // sPart[p] ready (~free now)
            asm volatile("bar.arrive 6, 64;" ::: "memory");   // slot credit to w5
            float pn2 = __ldcg(pPtr);
            const int np = p ^ 1;
            const float part = sPart[p][l];
            unsigned long long b0 = 0ull, b1 = 0ull;
            const ulonglong2* sp = reinterpret_cast<const ulonglong2*>(sbuf[p]);
#pragma unroll
            for (int m = 0; m < 8; m++) {
                ulonglong2 gg = sp[25 + m];
                fma2(b0, rva[2 * m], gg.x); fma2(b1, rva[2 * m + 1], gg.y);
            }
            add2(b0, b1);
            float lo, hi; unpack2(b0, lo, hi);
            float acc = part + lo + hi + pc;
            asm volatile("bar.sync 5, 160;" ::: "memory");    // credit from g+w4 (overlapped)
            const float val0 = tanh_hw(acc);
            {
                float t0 = cp0[0] * __shfl_sync(0xffffffffu, val0, 0);
                float t1 = cp0[1] * __shfl_sync(0xffffffffu, val0, 1);
                float t2 = cp0[2] * __shfl_sync(0xffffffffu, val0, 2);
                float t3 = cp0[3] * __shfl_sync(0xffffffffu, val0, 3);
                float t4 = cp0[4] * __shfl_sync(0xffffffffu, val0, 4);
                float t5 = cp0[5] * __shfl_sync(0xffffffffu, val0, 5);
                float t6 = cp0[6] * __shfl_sync(0xffffffffu, val0, 6);
                float t7 = cp0[7] * __shfl_sync(0xffffffffu, val0, 7);
                acc += ((t0 + t1) + (t2 + t3)) + ((t4 + t5) + (t6 + t7));
            }
            const float val1 = tanh_hw(acc);
            {
                float t0 = cp1[0] * __shfl_sync(0xffffffffu, val1, 8);
                float t1 = cp1[1] * __shfl_sync(0xffffffffu, val1, 9);
                float t2 = cp1[2] * __shfl_sync(0xffffffffu, val1, 10);
                float t3 = cp1[3] * __shfl_sync(0xffffffffu, val1, 11);
                float t4 = cp1[4] * __shfl_sync(0xffffffffu, val1, 12);
                float t5 = cp1[5] * __shfl_sync(0xffffffffu, val1, 13);
                float t6 = cp1[6] * __shfl_sync(0xffffffffu, val1, 14);
                float t7 = cp1[7] * __shfl_sync(0xffffffffu, val1, 15);
                acc += ((t0 + t1) + (t2 + t3)) + ((t4 + t5) + (t6 + t7));
            }
            const float val2 = tanh_hw(acc);
            {
                float t0 = cp2[0] * __shfl_sync(0xffffffffu, val2, 16);
                float t1 = cp2[1] * __shfl_sync(0xffffffffu, val2, 17);
                float t2 = cp2[2] * __shfl_sync(0xffffffffu, val2, 18);
                float t3 = cp2[3] * __shfl_sync(0xffffffffu, val2, 19);
                float t4 = cp2[4] * __shfl_sync(0xffffffffu, val2, 20);
                float t5 = cp2[5] * __shfl_sync(0xffffffffu, val2, 21);
                float t6 = cp2[6] * __shfl_sync(0xffffffffu, val2, 22);
                float t7 = cp2[7] * __shfl_sync(0xffffffffu, val2, 23);
                acc += ((t0 + t1) + (t2 + t3)) + ((t4 + t5) + (t6 + t7));
            }
            const float val3 = tanh_hw(acc);
            const float hv = (l < 8) ? val0 : (l < 16) ? val1 : (l < 24) ? val2 : val3;
            sbuf[np][100 + l] = hv;
            *hPtr = hv; hPtr += 32;
            asm volatile("bar.arrive 2, 160;" ::: "memory");  // publish h(S_{b+1})
            pc = pn; pn = pn2;
            if (b < NB4 - 3) pPtr += 32;
            p = np;
        }
    } else if (isG) {
        int p = 0;
        for (int b = 0; b < NB4; b++) {
            asm volatile("bar.sync 2, 160;" ::: "memory");    // h(S_b) ready
            asm volatile("bar.arrive 5, 160;" ::: "memory");  // credit to chain
            float pn2 = __ldcg(pPtr);
            const int np = p ^ 1;
            const ulonglong2* sp = reinterpret_cast<const ulonglong2*>(sbuf[p]);
#pragma unroll
            for (int q = 25; q < 33; q++) {
                ulonglong2 gg = sp[q];
                if (q & 1) { fma2(a2, rva[2 * q], gg.x); fma2(a3, rva[2 * q + 1], gg.y); }
                else       { fma2(a0, rva[2 * q], gg.x); fma2(a1, rva[2 * q + 1], gg.y); }
            }
            add2(a0, a1); add2(a2, a3); add2(a0, a2);
            float lo, hi; unpack2(a0, lo, hi);
            const float gn = lo + hi + pc;
            sbuf[np][tid] = gn;
            *gPtr = gn; gPtr += SD;
            asm volatile("bar.sync 3, 160;" ::: "memory");    // all c(S_{b+1}) stored
            a0 = 0ull; a1 = 0ull; a2 = 0ull; a3 = 0ull;
            const ulonglong2* sq = reinterpret_cast<const ulonglong2*>(sbuf[np]);
#pragma unroll
            for (int q = 0; q < 25; q++) {
                ulonglong2 gg = sq[q];
                if (q & 1) { fma2(a2, rva[2 * q], gg.x); fma2(a3, rva[2 * q + 1], gg.y); }
                else       { fma2(a0, rva[2 * q], gg.x); fma2(a1, rva[2 * q + 1], gg.y); }
            }
            pc = pn; pn = pn2;
            if (b < NB4 - 3) pPtr += SD;
            p = np;
        }
    } else if (isW4) {
        int p = 0;
        for (int b = 0; b < NB4; b++) {
            asm volatile("bar.sync 2, 160;" ::: "memory");
            asm volatile("bar.arrive 5, 160;" ::: "memory");  // credit to chain
            float pn2 = 0.f;
            if (pPtr) pn2 = __ldcg(pPtr);
            const int np = p ^ 1;
            const unsigned long long* s1 = reinterpret_cast<const unsigned long long*>(sbuf[p]);
#pragma unroll
            for (int k = 0; k < 9; k++) {
                const int idx = seg + 8 * k;
                if (idx >= 50 && idx < 66) fma2(a0, rva[k], s1[idx]);
            }
            float lo, hi; unpack2(a0, lo, hi);
            float v = lo + hi;
            v += __shfl_xor_sync(0xffffffffu, v, 1);
            v += __shfl_xor_sync(0xffffffffu, v, 2);
            v += __shfl_xor_sync(0xffffffffu, v, 4);
            if (seg == 0) {
                const float gn = v + pc;
                sbuf[np][96 + grp] = gn;
                *gPtr = gn;
            }
            gPtr += SD;
            asm volatile("bar.sync 3, 160;" ::: "memory");
            a0 = 0ull;
            const unsigned long long* s2 = reinterpret_cast<const unsigned long long*>(sbuf[np]);
#pragma unroll
            for (int k = 0; k < 9; k++) {
                const int idx = seg + 8 * k;
                if (idx < 50) fma2(a0, rva[k], s2[idx]);
            }
            pc = pn; pn = pn2;
            if (pPtr && b < NB4 - 3) pPtr += SD;
            p = np;
        }
    } else { // isP5: sPart_{b+1} = R' @ S_b, computed from sbuf[p] (already complete)
        int p = 0;
        for (int b = 0; b < NB4; b++) {
            const int np = p ^ 1;
            unsigned long long b0 = 0ull, b1 = 0ull, b2 = 0ull, b3 = 0ull;
            const ulonglong2* sq = reinterpret_cast<const ulonglong2*>(sbuf[p]);
#pragma unroll
            for (int q = 0; q < 33; q++) {
                ulonglong2 gg = sq[q];
                if (q & 1) { fma2(b2, rva[2 * q], gg.x); fma2(b3, rva[2 * q + 1], gg.y); }
                else       { fma2(b0, rva[2 * q], gg.x); fma2(b1, rva[2 * q + 1], gg.y); }
            }
            add2(b0, b1); add2(b2, b3); add2(b0, b2);
            float lo, hi; unpack2(b0, lo, hi);
            const float val = lo + hi;
            asm volatile("bar.sync 6, 64;" ::: "memory");     // chain freed slot np
            sPart[np][l] = val;
            asm volatile("bar.arrive 4, 64;" ::: "memory");   // sPart_{b+1} ready
            asm volatile("bar.sync 3, 160;" ::: "memory");    // pace with phase b
            p = np;
        }
    }
}

// ============================================================================
// 4) post: reconstruct c_{4m+1..3} from anchors + h; anchor m+1 row; y.
// ============================================================================
__global__ void __launch_bounds__(128, 1) post_kernel(
    const float* __restrict__ w, const float* __restrict__ u,
    const float* __restrict__ Bw, const float* __restrict__ W2,
    const float* __restrict__ b2, const int* __restrict__ obs,
    float* __restrict__ outc, float* __restrict__ outy)
{
    __shared__ __align__(16) float4 at4s[SD * 25];
    __shared__ __align__(16) float va[SD];
    __shared__ float hh[32];
    __shared__ int obsS[NOBS];

    const int tid = threadIdx.x;
    const float4* gAt4 = reinterpret_cast<const float4*>(g_At4);
    for (int o = tid; o < SD * 25; o += 128) at4s[o] = gAt4[o];
    if (tid < NOBS) obsS[tid] = obs[tid];

    float bwx = 0.f, bwy = 0.f, db2 = 0.f, w2r[HID];
#pragma unroll
    for (int z = 0; z < HID; z++) w2r[z] = 0.f;
    if (tid < SD) {
        bwx = Bw[tid * 2]; bwy = Bw[tid * 2 + 1]; db2 = DTC * b2[tid];
#pragma unroll
        for (int z = 0; z < HID; z++) w2r[z] = DTC * W2[tid * HID + z];
    }
    __syncthreads();

    const float4* va4 = reinterpret_cast<const float4*>(va);

    for (int gi = 0; gi < GQ; gi++) {
        const int m = blockIdx.x * GQ + gi;
        const int t0 = 4 * m;

        if (tid < 32) hh[tid] = g_h[(size_t)(t0 + 1 + (tid >> 3)) * HID + (tid & 7)];
        if (tid < SD) va[tid] = g_G[(size_t)m * SD + tid];
        __syncthreads();
#pragma unroll
        for (int s = 1; s <= 3; s++) {
            const int t = t0 + s;
            float cv = 0.f;
            if (tid < SD) {
                cv = matvec100(at4s, va4, tid)
                   + bwx * w[2 * (t - 1)] + bwy * w[2 * (t - 1) + 1]
                   + u[(size_t)(t - 1) * SD + tid] + db2;
#pragma unroll
                for (int z = 0; z < HID; z++) cv += w2r[z] * hh[8 * (s - 1) + z];
            }
            __syncthreads();
            if (tid < SD) {
                va[tid] = cv;
                outc[(size_t)(t - 1) * SD + tid] = cv;
            }
            __syncthreads();
            if (tid < NOBS) outy[(size_t)(t - 1) * NOBS + tid] = va[obsS[tid]];
        }
        __syncthreads();
        if (tid < SD) {
            float cv = g_G[(size_t)(m + 1) * SD + tid];
            va[tid] = cv;
            outc[(size_t)(t0 + 3) * SD + tid] = cv;
        }
        __syncthreads();
        if (tid < NOBS) outy[(size_t)(t0 + 3) * NOBS + tid] = va[obsS[tid]];
        __syncthreads();
    }
}

extern "C" void kernel_launch(void* const* d_in, const int* in_sizes, int n_in,
                              void* d_out, int out_size) {
    const float* c0  = (const float*)d_in[0];
    const float* w   = (const float*)d_in[1];
    const float* u   = (const float*)d_in[2];
    const float* A   = (const float*)d_in[3];
    const float* Bw  = (const float*)d_in[4];
    const float* W1  = (const float*)d_in[5];
    const float* b1  = (const float*)d_in[6];
    const float* W2  = (const float*)d_in[7];
    const float* b2  = (const float*)d_in[8];
    const int*   ob  = (const int*)d_in[9];

    float* outc = (float*)d_out;                      // (T, 100)
    float* outy = (float*)d_out + (size_t)TT * SD;    // (T, 12)

    setup1_kernel<<<1, 128>>>(A, Bw, W1, b1, W2, b2, c0, w, u);
    setup2_kernel<<<1, 128>>>(A, W1, W2);
    setup3_kernel<<<1, 128>>>(c0);
    precomp_kernel<<<PRE_CTAS, 128>>>(w, u, Bw, W1, b1, b2);
    fold_kernel<<<PRE_CTAS, 128>>>();
    serial_kernel<<<1, 192>>>(c0);
    post_kernel<<<POST_CTAS, 128>>>(w, u, Bw, W2, b2, ob, outc, outy);
}